// round 8
// baseline (speedup 1.0000x reference)
#include <cuda_runtime.h>
#include <cuda_bf16.h>
#include <cstdint>
#include <cstring>
#include <math.h>

#define NB 4096
#define NT 8192
#define DD 256
#define CC 31
#define NTILES_M 64
#define GRID_MAIN 4160     // sum_{ti<64} (128 - 2*ti)

// ======================= device scratch =======================
__device__ float  g_sq[NT];
__device__ float  g_colpart[1024][DD];
__device__ float  g_tpart[512][32];
__device__ int    g_scnt_part[512][32];
__device__ int    g_tpres_part[512][32];
__device__ float  g_sScale[32];
__device__ float  g_tScale[32];
__device__ float  g_coef[5];
__device__ float  g_c0;
__device__ int    g_chain;
__device__ float  g_inv_nidx;
__device__ double g_loss;

__device__ __align__(16) unsigned short g_Xh[NT * DD];
__device__ __align__(16) unsigned short g_Xl[NT * DD];
__device__ __align__(16) unsigned short g_Vh[NT * 32];
__device__ __align__(16) unsigned short g_Vl[NT * 32];

// ======================= helpers =======================
__device__ __forceinline__ float ex2f(float x) {
    float y; asm("ex2.approx.ftz.f32 %0, %1;" : "=f"(y) : "f"(x)); return y;
}
__device__ __forceinline__ uint32_t smem_u32(const void* p) {
    uint32_t a;
    asm("{ .reg .u64 t; cvta.to.shared.u64 t, %1; cvt.u32.u64 %0, t; }" : "=r"(a) : "l"(p));
    return a;
}
#define CP16(dst, src) \
    asm volatile("cp.async.cg.shared.global [%0], [%1], 16;" :: "r"(dst), "l"(src))
#define CP_COMMIT() asm volatile("cp.async.commit_group;" ::: "memory")
#define CP_WAIT1()  asm volatile("cp.async.wait_group 1;" ::: "memory")
#define CP_WAIT0()  asm volatile("cp.async.wait_group 0;" ::: "memory")

__device__ __forceinline__ void ldsm4(uint32_t r[4], uint32_t addr) {
    asm volatile("ldmatrix.sync.aligned.m8n8.x4.shared.b16 {%0,%1,%2,%3}, [%4];"
        : "=r"(r[0]), "=r"(r[1]), "=r"(r[2]), "=r"(r[3]) : "r"(addr));
}
__device__ __forceinline__ void mma16816(float d[4], const uint32_t a[4], const uint32_t b[2]) {
    asm volatile("mma.sync.aligned.m16n8k16.row.col.f32.bf16.bf16.f32 "
        "{%0,%1,%2,%3}, {%4,%5,%6,%7}, {%8,%9}, {%0,%1,%2,%3};"
        : "+f"(d[0]), "+f"(d[1]), "+f"(d[2]), "+f"(d[3])
        : "r"(a[0]), "r"(a[1]), "r"(a[2]), "r"(a[3]), "r"(b[0]), "r"(b[1]));
}

// ======================= smem layout (k_main) =======================
// Rows are 128B: hi in segs 0-3, lo in segs 4-7 (chunk of 32 bf16 cols).
#define SM_VA   0                  // 128 rows x 128B = 16KB
#define SM_VB   16384              // 64 rows x 128B = 8KB
#define SM_S    24576              // 3 stages x (A 16KB + B 8KB) = 72KB
#define STAGE_SZ 24576
#define SM_SQA  98304
#define SM_SQB  98816
#define SM_RED  99072
#define SMEM_TOTAL 99136

// ======================= K1: fused prepass =======================
// 1024 CTAs x 256 thr; warp w handles row bid*8+w; lane covers 8 cols.
__global__ void __launch_bounds__(256) k_prep(
        const float* __restrict__ src, const float* __restrict__ tgt,
        const int* __restrict__ s_label, const float* __restrict__ t_label) {
    __shared__ float scol[8][DD];
    __shared__ float stsum[8][32];
    __shared__ int   sharg[8];
    __shared__ int   scnt[32];
    int b = blockIdx.x, t = threadIdx.x, w = t >> 5, l = t & 31;
    int row = b * 8 + w;
    const float* rp = (row < NB) ? src + (size_t)row * DD : tgt + (size_t)(row - NB) * DD;

    float4 x0 = *(const float4*)(rp + l * 8);
    float4 x1 = *(const float4*)(rp + l * 8 + 4);
    float xs[8] = {x0.x, x0.y, x0.z, x0.w, x1.x, x1.y, x1.z, x1.w};

    // squared norm
    float s = 0.f;
#pragma unroll
    for (int k = 0; k < 8; k++) s = fmaf(xs[k], xs[k], s);
#pragma unroll
    for (int off = 16; off; off >>= 1) s += __shfl_xor_sync(0xffffffffu, s, off);
    if (l == 0) g_sq[row] = s;

    // hi/lo split
    unsigned short h[8], lo[8];
#pragma unroll
    for (int k = 0; k < 8; k++) {
        __nv_bfloat16 hb = __float2bfloat16(xs[k]);
        float rest = xs[k] - __bfloat162float(hb);
        __nv_bfloat16 lb = __float2bfloat16(rest);
        memcpy(&h[k], &hb, 2); memcpy(&lo[k], &lb, 2);
    }
    size_t e = (size_t)row * DD + l * 8;
    *(uint2*)(g_Xh + e)     = make_uint2((uint32_t)h[0] | ((uint32_t)h[1] << 16),
                                         (uint32_t)h[2] | ((uint32_t)h[3] << 16));
    *(uint2*)(g_Xh + e + 4) = make_uint2((uint32_t)h[4] | ((uint32_t)h[5] << 16),
                                         (uint32_t)h[6] | ((uint32_t)h[7] << 16));
    *(uint2*)(g_Xl + e)     = make_uint2((uint32_t)lo[0] | ((uint32_t)lo[1] << 16),
                                         (uint32_t)lo[2] | ((uint32_t)lo[3] << 16));
    *(uint2*)(g_Xl + e + 4) = make_uint2((uint32_t)lo[4] | ((uint32_t)lo[5] << 16),
                                         (uint32_t)lo[6] | ((uint32_t)lo[7] << 16));

    // column-sum partials (per-warp slice, deterministic)
#pragma unroll
    for (int k = 0; k < 8; k++) scol[w][l * 8 + k] = xs[k];
    __syncthreads();
    {
        float m = 0.f;
#pragma unroll
        for (int ww = 0; ww < 8; ww++) m += scol[ww][t];
        g_colpart[b][t] = m;
    }

    // label statistics
    if (b < 512) {
        if (t < 32) scnt[t] = 0;
        __syncthreads();
        if (l == 0) {
            int lbl = s_label[row];
            if ((unsigned)lbl < CC) atomicAdd(&scnt[lbl], 1);
        }
        __syncthreads();
        if (t < 32) g_scnt_part[b][t] = scnt[t];
    } else {
        int tb = b - 512;
        int trow = row - NB;
        const float* tr = t_label + (size_t)trow * CC;
        float v = (l < CC) ? tr[l] : -1e30f;
        stsum[w][l] = (l < CC) ? v : 0.f;
        // warp argmax (first-max tie-break)
        float bv = v; int bi = l;
#pragma unroll
        for (int off = 16; off; off >>= 1) {
            float ov = __shfl_xor_sync(0xffffffffu, bv, off);
            int   oi = __shfl_xor_sync(0xffffffffu, bi, off);
            if (ov > bv || (ov == bv && oi < bi)) { bv = ov; bi = oi; }
        }
        if (l == 0) sharg[w] = bi;
        __syncthreads();
        if (t < 32) {
            float tc = 0.f; int pres = 0;
#pragma unroll
            for (int ww = 0; ww < 8; ww++) {
                tc += stsum[ww][t];
                pres |= (sharg[ww] == t);
            }
            g_tpart[tb][t] = tc;
            g_tpres_part[tb][t] = pres;
        }
    }
}

// ======================= K2: finalize scalars =======================
__global__ void k_finalize() {
    __shared__ double red[256];
    __shared__ double sMSQ;
    int t = threadIdx.x;

    float m = 0.f;
    for (int b = 0; b < 1024; b++) m += g_colpart[b][t];
    red[t] = (double)m * (double)m;
    __syncthreads();
    for (int off = 128; off; off >>= 1) { if (t < off) red[t] += red[t + off]; __syncthreads(); }
    if (t == 0) sMSQ = red[0];
    __syncthreads();

    double s1 = 0.0;
    for (int r = t; r < NT; r += 256) s1 += (double)g_sq[r];
    red[t] = s1;
    __syncthreads();
    for (int off = 128; off; off >>= 1) { if (t < off) red[t] += red[t + off]; __syncthreads(); }

    if (t == 0) {
        g_loss = 0.0;
        double S1 = red[0], MSQ = sMSQ;
        double sum_l2 = 2.0 * (double)NT * S1 - 2.0 * MSQ;
        double bw = sum_l2 / ((double)NT * (double)NT - (double)NT);
        if (bw < 1e-6) bw = 1e-6;
        bw *= 0.25;
        g_chain = (bw >= 1e-6) ? 1 : 0;
        const double L2E = 1.4426950408889634;
        for (int i = 0; i < 5; i++) {
            double den = bw * (double)(1 << i);
            if (den < 1e-6) den = 1e-6;
            g_coef[i] = (float)(L2E / den);
        }
        g_c0 = g_coef[4];
    }
    __syncthreads();
    if (t == 0) {
        int nidx = 0;
        for (int c = 0; c < CC; c++) {
            int cnt = 0, pres = 0;
            float tc = 0.f;
            for (int b = 0; b < 512; b++) {
                cnt += g_scnt_part[b][c];
                pres |= g_tpres_part[b][c];
                tc += g_tpart[b][c];
            }
            int msk = (cnt > 0) && pres;
            nidx += msk;
            g_sScale[c] = msk ? 1.0f / (float)cnt : 0.f;
            float tdiv = (tc == 0.f) ? 100.f : tc;
            g_tScale[c] = msk ? 1.0f / tdiv : 0.f;
        }
        g_sScale[31] = 0.f; g_tScale[31] = 0.f;
        if (nidx < 1) nidx = 1;
        g_inv_nidx = 1.0f / (float)nidx;
    }
}

// ======================= K3: build signed weight vectors =======================
__global__ void k_buildV(const int* __restrict__ s_label, const float* __restrict__ t_label) {
    int i = blockIdx.x * 256 + threadIdx.x;
    float v[32];
    if (i < NB) {
#pragma unroll
        for (int c = 0; c < 32; c++) v[c] = 0.f;
        int lbl = s_label[i];
        if ((unsigned)lbl < CC) v[lbl] = g_sScale[lbl];
    } else {
        const float* tr = t_label + (size_t)(i - NB) * CC;
#pragma unroll
        for (int c = 0; c < CC; c++) v[c] = -tr[c] * g_tScale[c];
        v[31] = 0.f;
    }
    unsigned short* vh = g_Vh + (size_t)i * 32;
    unsigned short* vl = g_Vl + (size_t)i * 32;
#pragma unroll
    for (int c = 0; c < 32; c++) {
        __nv_bfloat16 hb = __float2bfloat16(v[c]);
        float rest = v[c] - __bfloat162float(hb);
        __nv_bfloat16 lb = __float2bfloat16(rest);
        unsigned short hu, lu; memcpy(&hu, &hb, 2); memcpy(&lu, &lb, 2);
        vh[c] = hu; vl[c] = lu;
    }
}

// ======================= K4: main tile kernel (128M x 64N, 2 CTAs/SM) ==========
__device__ __forceinline__ void issue_chunk(uint32_t sb, uint32_t stageOff,
        const unsigned short* Ah, const unsigned short* Al,
        const unsigned short* Bh, const unsigned short* Bl,
        int chunk, int tid) {
    // A: 128 rows x 8 segs (4 hi + 4 lo) = 1024 CP16
#pragma unroll
    for (int q = 0; q < 4; q++) {
        int idx = tid + 256 * q;
        int row = idx >> 3, seg = idx & 7;
        const unsigned short* srcp = ((seg < 4) ? Ah : Al) + row * 256 + chunk * 32 + (seg & 3) * 8;
        uint32_t dst = sb + stageOff + row * 128 + ((seg ^ (row & 7)) << 4);
        CP16(dst, srcp);
    }
    // B: 64 rows x 8 segs = 512 CP16
#pragma unroll
    for (int q = 0; q < 2; q++) {
        int idx = tid + 256 * q;
        int row = idx >> 3, seg = idx & 7;
        const unsigned short* srcp = ((seg < 4) ? Bh : Bl) + row * 256 + chunk * 32 + (seg & 3) * 8;
        uint32_t dst = sb + stageOff + 16384 + row * 128 + ((seg ^ (row & 7)) << 4);
        CP16(dst, srcp);
    }
}

// 3-product (hh + hl + lh) over 2 ksteps of 16 on packed hi/lo rows.
__device__ __forceinline__ void do_mma32(uint32_t aB, uint32_t bB,
                                         int wm, int wn, int lane, float acc[2][4][4]) {
    int r16 = lane & 15;
    int cuA = lane >> 4;
    int cuB = (lane >> 3) & 1;
    int jrow = (lane >> 4) * 8;
#pragma unroll
    for (int ks = 0; ks < 2; ks++) {
        uint32_t ah[2][4], al[2][4], bh[2][4], bl[2][4];
#pragma unroll
        for (int i = 0; i < 2; i++) {
            int row = wm * 32 + i * 16 + r16;
            int sh = ks * 2 + cuA;
            ldsm4(ah[i], aB + row * 128 + ((sh ^ (row & 7)) << 4));
            ldsm4(al[i], aB + row * 128 + (((sh + 4) ^ (row & 7)) << 4));
        }
#pragma unroll
        for (int p = 0; p < 2; p++) {
            int row = wn * 32 + p * 16 + jrow + (lane & 7);
            int sh = ks * 2 + cuB;
            ldsm4(bh[p], bB + row * 128 + ((sh ^ (row & 7)) << 4));
            ldsm4(bl[p], bB + row * 128 + (((sh + 4) ^ (row & 7)) << 4));
        }
#pragma unroll
        for (int i = 0; i < 2; i++)
#pragma unroll
            for (int j = 0; j < 4; j++) {
                const uint32_t* fh = &bh[j >> 1][(j & 1) * 2];
                const uint32_t* fl = &bl[j >> 1][(j & 1) * 2];
                mma16816(acc[i][j], ah[i], fh);
                mma16816(acc[i][j], ah[i], fl);
                mma16816(acc[i][j], al[i], fh);
            }
    }
}

__global__ void __launch_bounds__(256, 2) k_main() {
    extern __shared__ __align__(1024) char smem[];
    uint32_t sb = smem_u32(smem);
    int tid = threadIdx.x, wid = tid >> 5, lane = tid & 31;
    int wm = wid & 3, wn = wid >> 2;       // 4 M-warps x 2 N-warps

    // decode (ti, jj): jj in [2*ti, 127]
    int bid = blockIdx.x, ti = 0, rem = bid;
    while (rem >= 128 - 2 * ti) { rem -= 128 - 2 * ti; ti++; }
    int jj = 2 * ti + rem;
    int rA = ti * 128, rB = jj * 64;

    float* ssqa = (float*)(smem + SM_SQA);
    float* ssqb = (float*)(smem + SM_SQB);
    float* sred = (float*)(smem + SM_RED);
    if (tid < 128) ssqa[tid] = g_sq[rA + tid];
    else if (tid < 192) ssqb[tid - 128] = g_sq[rB + tid - 128];

    const unsigned short* Ah = g_Xh + (size_t)rA * 256;
    const unsigned short* Al = g_Xl + (size_t)rA * 256;
    const unsigned short* Bh = g_Xh + (size_t)rB * 256;
    const unsigned short* Bl = g_Xl + (size_t)rB * 256;

    // group0: V (packed) + chunk0 -> stage0
    {
#pragma unroll
        for (int q = 0; q < 4; q++) {           // VA: 1024 CP16
            int idx = tid + 256 * q;
            int row = idx >> 3, seg = idx & 7;
            const unsigned short* srcp = ((seg < 4) ? g_Vh : g_Vl) + (size_t)(rA + row) * 32 + (seg & 3) * 8;
            CP16(sb + SM_VA + row * 128 + ((seg ^ (row & 7)) << 4), srcp);
        }
#pragma unroll
        for (int q = 0; q < 2; q++) {           // VB: 512 CP16
            int idx = tid + 256 * q;
            int row = idx >> 3, seg = idx & 7;
            const unsigned short* srcp = ((seg < 4) ? g_Vh : g_Vl) + (size_t)(rB + row) * 32 + (seg & 3) * 8;
            CP16(sb + SM_VB + row * 128 + ((seg ^ (row & 7)) << 4), srcp);
        }
        issue_chunk(sb, SM_S + 0 * STAGE_SZ, Ah, Al, Bh, Bl, 0, tid);
        CP_COMMIT();
    }
    issue_chunk(sb, SM_S + 1 * STAGE_SZ, Ah, Al, Bh, Bl, 1, tid);
    CP_COMMIT();

    float acc[2][4][4], wacc[2][4][4];
#pragma unroll
    for (int i = 0; i < 2; i++)
#pragma unroll
        for (int j = 0; j < 4; j++)
#pragma unroll
            for (int r = 0; r < 4; r++) { acc[i][j][r] = 0.f; wacc[i][j][r] = 0.f; }

#pragma unroll 1
    for (int c = 0; c < 8; c++) {
        if (c < 7) { CP_WAIT1(); } else { CP_WAIT0(); }
        __syncthreads();
        if (c < 6) {
            issue_chunk(sb, SM_S + ((c + 2) % 3) * STAGE_SZ, Ah, Al, Bh, Bl, c + 2, tid);
            CP_COMMIT();
        }
        uint32_t st = sb + SM_S + (c % 3) * STAGE_SZ;
        do_mma32(st, st + 16384, wm, wn, lane, acc);
    }

    // W = Va . Vb^T (V loaded with group0, long since complete)
    do_mma32(sb + SM_VA, sb + SM_VB, wm, wn, lane, wacc);

    // ---- epilogue ----
    float sqa_r[4], sqb_c[8];
    int grow[4], gcol[8];
#pragma unroll
    for (int i = 0; i < 2; i++)
#pragma unroll
        for (int rh = 0; rh < 2; rh++) {
            int rl = i * 16 + (lane >> 2) + rh * 8;
            sqa_r[i * 2 + rh] = ssqa[wm * 32 + rl];
            grow[i * 2 + rh]  = rA + wm * 32 + rl;
        }
#pragma unroll
    for (int j = 0; j < 4; j++)
#pragma unroll
        for (int cc2 = 0; cc2 < 2; cc2++) {
            int cl = j * 8 + (lane & 3) * 2 + cc2;
            sqb_c[j * 2 + cc2] = ssqb[wn * 32 + cl];
            gcol[j * 2 + cc2]  = rB + wn * 32 + cl;
        }

    float c0 = g_c0;
    int chain = g_chain;
    float cf0 = 0, cf1 = 0, cf2 = 0, cf3 = 0, cf4 = 0;
    if (!chain) { cf0 = g_coef[0]; cf1 = g_coef[1]; cf2 = g_coef[2]; cf3 = g_coef[3]; cf4 = g_coef[4]; }

    float part = 0.f;
#pragma unroll
    for (int i = 0; i < 2; i++)
#pragma unroll
        for (int j = 0; j < 4; j++)
#pragma unroll
            for (int r = 0; r < 4; r++) {
                int gr = grow[i * 2 + (r >> 1)];
                int gc = gcol[j * 2 + (r & 1)];
                float f = (gc > gr) ? 2.0f : ((gc == gr) ? 1.0f : 0.0f);
                float l2 = fmaf(-2.0f, acc[i][j][r], sqa_r[i * 2 + (r >> 1)] + sqb_c[j * 2 + (r & 1)]);
                l2 = fmaxf(l2, 0.0f);
                float ks;
                if (chain) {
                    float x  = ex2f(-l2 * c0);
                    float x2 = x * x, x4 = x2 * x2, x8 = x4 * x4;
                    ks = x + x2 + x4 + x8 + x8 * x8;
                } else {
                    ks = ex2f(-l2 * cf0) + ex2f(-l2 * cf1) + ex2f(-l2 * cf2)
                       + ex2f(-l2 * cf3) + ex2f(-l2 * cf4);
                }
                part = fmaf(ks, wacc[i][j][r] * f, part);
            }

#pragma unroll
    for (int off = 16; off; off >>= 1) part += __shfl_xor_sync(0xffffffffu, part, off);
    if (lane == 0) sred[wid] = part;
    __syncthreads();
    if (tid == 0) {
        float s = 0.f;
#pragma unroll
        for (int w = 0; w < 8; w++) s += sred[w];
        atomicAdd(&g_loss, (double)s);
    }
}

__global__ void k_out(float* out) {
    out[0] = (float)(g_loss * (double)g_inv_nidx);
}

// ======================= launch =======================
extern "C" void kernel_launch(void* const* d_in, const int* in_sizes, int n_in,
                              void* d_out, int out_size) {
    const float* src = (const float*)d_in[0];
    const float* tgt = (const float*)d_in[1];
    const int*   sl  = (const int*)d_in[2];
    const float* tl  = (const float*)d_in[3];
    float* out = (float*)d_out;

    cudaFuncSetAttribute(k_main, cudaFuncAttributeMaxDynamicSharedMemorySize, SMEM_TOTAL);

    k_prep<<<1024, 256>>>(src, tgt, sl, tl);
    k_finalize<<<1, 256>>>();
    k_buildV<<<32, 256>>>(sl, tl);
    k_main<<<GRID_MAIN, 256, SMEM_TOTAL>>>();
    k_out<<<1, 1>>>(out);
}

// round 9
// speedup vs baseline: 3.6469x; 3.6469x over previous
#include <cuda_runtime.h>
#include <cuda_bf16.h>
#include <cstdint>
#include <cstring>
#include <math.h>

#define NB 4096
#define NT 8192
#define DD 256
#define CC 31
#define TILES 64
#define NTILEPAIRS 2080

// ======================= device scratch =======================
__device__ float  g_sq[NT];
__device__ float  g_colpart[1024][DD];
__device__ float  g_tpart[512][32];
__device__ int    g_scnt_part[512][32];
__device__ int    g_tpres_part[512][32];
__device__ float  g_sScale[32];
__device__ float  g_tScale[32];
__device__ float  g_coef[5];
__device__ float  g_c0;
__device__ int    g_chain;
__device__ float  g_inv_nidx;
__device__ double g_loss;

__device__ __align__(16) unsigned short g_Xh[NT * DD];
__device__ __align__(16) unsigned short g_Xl[NT * DD];
__device__ __align__(16) unsigned short g_Vh[NT * 32];
__device__ __align__(16) unsigned short g_Vl[NT * 32];

// ======================= helpers =======================
__device__ __forceinline__ float ex2f(float x) {
    float y; asm("ex2.approx.ftz.f32 %0, %1;" : "=f"(y) : "f"(x)); return y;
}
__device__ __forceinline__ uint32_t smem_u32(const void* p) {
    uint32_t a;
    asm("{ .reg .u64 t; cvta.to.shared.u64 t, %1; cvt.u32.u64 %0, t; }" : "=r"(a) : "l"(p));
    return a;
}
#define CP16(dst, src) \
    asm volatile("cp.async.cg.shared.global [%0], [%1], 16;" :: "r"(dst), "l"(src))
#define CP_COMMIT() asm volatile("cp.async.commit_group;" ::: "memory")
#define CP_WAIT1()  asm volatile("cp.async.wait_group 1;" ::: "memory")
#define CP_WAIT0()  asm volatile("cp.async.wait_group 0;" ::: "memory")

__device__ __forceinline__ void ldsm4(uint32_t r[4], uint32_t addr) {
    asm volatile("ldmatrix.sync.aligned.m8n8.x4.shared.b16 {%0,%1,%2,%3}, [%4];"
        : "=r"(r[0]), "=r"(r[1]), "=r"(r[2]), "=r"(r[3]) : "r"(addr));
}
__device__ __forceinline__ void mma16816(float d[4], const uint32_t a[4], const uint32_t b[2]) {
    asm volatile("mma.sync.aligned.m16n8k16.row.col.f32.bf16.bf16.f32 "
        "{%0,%1,%2,%3}, {%4,%5,%6,%7}, {%8,%9}, {%0,%1,%2,%3};"
        : "+f"(d[0]), "+f"(d[1]), "+f"(d[2]), "+f"(d[3])
        : "r"(a[0]), "r"(a[1]), "r"(a[2]), "r"(a[3]), "r"(b[0]), "r"(b[1]));
}

// ======================= smem layout (k_main) =======================
// V packed: hi in segs 0-3, lo in segs 4-7 per 128B row. VA, VB 16KB each.
#define SM_VA   0
#define SM_VB   16384
#define SM_S0   32768
#define SM_S1   (32768 + 65536)
#define SM_S2   (32768 + 2 * 65536)
#define SM_SQA  229376
#define SM_SQB  229888
#define SM_RED  230400
#define SMEM_TOTAL 230464

// ======================= K1: fused prepass (1024 CTAs) =======================
__global__ void __launch_bounds__(256) k_prep(
        const float* __restrict__ src, const float* __restrict__ tgt,
        const int* __restrict__ s_label, const float* __restrict__ t_label) {
    __shared__ float scol[8][DD];
    __shared__ float stsum[8][32];
    __shared__ int   sharg[8];
    __shared__ int   scnt[32];
    int b = blockIdx.x, t = threadIdx.x, w = t >> 5, l = t & 31;
    int row = b * 8 + w;
    const float* rp = (row < NB) ? src + (size_t)row * DD : tgt + (size_t)(row - NB) * DD;

    float4 x0 = *(const float4*)(rp + l * 8);
    float4 x1 = *(const float4*)(rp + l * 8 + 4);
    float xs[8] = {x0.x, x0.y, x0.z, x0.w, x1.x, x1.y, x1.z, x1.w};

    float s = 0.f;
#pragma unroll
    for (int k = 0; k < 8; k++) s = fmaf(xs[k], xs[k], s);
#pragma unroll
    for (int off = 16; off; off >>= 1) s += __shfl_xor_sync(0xffffffffu, s, off);
    if (l == 0) g_sq[row] = s;

    unsigned short h[8], lo[8];
#pragma unroll
    for (int k = 0; k < 8; k++) {
        __nv_bfloat16 hb = __float2bfloat16(xs[k]);
        float rest = xs[k] - __bfloat162float(hb);
        __nv_bfloat16 lb = __float2bfloat16(rest);
        memcpy(&h[k], &hb, 2); memcpy(&lo[k], &lb, 2);
    }
    size_t e = (size_t)row * DD + l * 8;
    *(uint2*)(g_Xh + e)     = make_uint2((uint32_t)h[0] | ((uint32_t)h[1] << 16),
                                         (uint32_t)h[2] | ((uint32_t)h[3] << 16));
    *(uint2*)(g_Xh + e + 4) = make_uint2((uint32_t)h[4] | ((uint32_t)h[5] << 16),
                                         (uint32_t)h[6] | ((uint32_t)h[7] << 16));
    *(uint2*)(g_Xl + e)     = make_uint2((uint32_t)lo[0] | ((uint32_t)lo[1] << 16),
                                         (uint32_t)lo[2] | ((uint32_t)lo[3] << 16));
    *(uint2*)(g_Xl + e + 4) = make_uint2((uint32_t)lo[4] | ((uint32_t)lo[5] << 16),
                                         (uint32_t)lo[6] | ((uint32_t)lo[7] << 16));

#pragma unroll
    for (int k = 0; k < 8; k++) scol[w][l * 8 + k] = xs[k];
    __syncthreads();
    {
        float m = 0.f;
#pragma unroll
        for (int ww = 0; ww < 8; ww++) m += scol[ww][t];
        g_colpart[b][t] = m;
    }

    if (b < 512) {
        if (t < 32) scnt[t] = 0;
        __syncthreads();
        if (l == 0) {
            int lbl = s_label[row];
            if ((unsigned)lbl < CC) atomicAdd(&scnt[lbl], 1);
        }
        __syncthreads();
        if (t < 32) g_scnt_part[b][t] = scnt[t];
    } else {
        int tb = b - 512;
        const float* tr = t_label + (size_t)(row - NB) * CC;
        float v = (l < CC) ? tr[l] : -1e30f;
        stsum[w][l] = (l < CC) ? v : 0.f;
        float bv = v; int bi = l;
#pragma unroll
        for (int off = 16; off; off >>= 1) {
            float ov = __shfl_xor_sync(0xffffffffu, bv, off);
            int   oi = __shfl_xor_sync(0xffffffffu, bi, off);
            if (ov > bv || (ov == bv && oi < bi)) { bv = ov; bi = oi; }
        }
        if (l == 0) sharg[w] = bi;
        __syncthreads();
        if (t < 32) {
            float tc = 0.f; int pres = 0;
#pragma unroll
            for (int ww = 0; ww < 8; ww++) {
                tc += stsum[ww][t];
                pres |= (sharg[ww] == t);
            }
            g_tpart[tb][t] = tc;
            g_tpres_part[tb][t] = pres;
        }
    }
}

// ======================= K2: finalize (fully parallel) =======================
__global__ void k_finalize() {
    __shared__ double red[256];
    __shared__ double sMSQ;
    int t = threadIdx.x;

    // MSQ = || column sums ||^2 (coalesced: thread t owns column t)
    float m = 0.f;
    for (int b = 0; b < 1024; b++) m += g_colpart[b][t];
    red[t] = (double)m * (double)m;
    __syncthreads();
    for (int off = 128; off; off >>= 1) { if (t < off) red[t] += red[t + off]; __syncthreads(); }
    if (t == 0) sMSQ = red[0];
    __syncthreads();

    double s1 = 0.0;
    for (int r = t; r < NT; r += 256) s1 += (double)g_sq[r];
    red[t] = s1;
    __syncthreads();
    for (int off = 128; off; off >>= 1) { if (t < off) red[t] += red[t + off]; __syncthreads(); }

    // label reduction: warp 0, lane = class (coalesced over 512 partial blocks)
    if (t < 32) {
        int cnt = 0, pres = 0;
        float tc = 0.f;
        for (int b = 0; b < 512; b++) {
            cnt  += g_scnt_part[b][t];
            pres |= g_tpres_part[b][t];
            tc   += g_tpart[b][t];
        }
        int msk = (t < CC) && (cnt > 0) && pres;
        unsigned bal = __ballot_sync(0xffffffffu, msk);
        int nidx = __popc(bal);
        if (nidx < 1) nidx = 1;
        g_sScale[t] = msk ? 1.0f / (float)cnt : 0.f;
        float tdiv = (tc == 0.f) ? 100.f : tc;
        g_tScale[t] = msk ? 1.0f / tdiv : 0.f;
        if (t == 0) g_inv_nidx = 1.0f / (float)nidx;
    }

    if (t == 0) {
        g_loss = 0.0;
        double S1 = red[0], MSQ = sMSQ;
        double sum_l2 = 2.0 * (double)NT * S1 - 2.0 * MSQ;
        double bw = sum_l2 / ((double)NT * (double)NT - (double)NT);
        if (bw < 1e-6) bw = 1e-6;
        bw *= 0.25;
        g_chain = (bw >= 1e-6) ? 1 : 0;
        const double L2E = 1.4426950408889634;
        for (int i = 0; i < 5; i++) {
            double den = bw * (double)(1 << i);
            if (den < 1e-6) den = 1e-6;
            g_coef[i] = (float)(L2E / den);
        }
        g_c0 = g_coef[4];
    }
}

// ======================= K3: build signed weight vectors =======================
__global__ void k_buildV(const int* __restrict__ s_label, const float* __restrict__ t_label) {
    int i = blockIdx.x * 256 + threadIdx.x;
    float v[32];
    if (i < NB) {
#pragma unroll
        for (int c = 0; c < 32; c++) v[c] = 0.f;
        int lbl = s_label[i];
        if ((unsigned)lbl < CC) v[lbl] = g_sScale[lbl];
    } else {
        const float* tr = t_label + (size_t)(i - NB) * CC;
#pragma unroll
        for (int c = 0; c < CC; c++) v[c] = -tr[c] * g_tScale[c];
        v[31] = 0.f;
    }
    unsigned short* vh = g_Vh + (size_t)i * 32;
    unsigned short* vl = g_Vl + (size_t)i * 32;
#pragma unroll
    for (int c = 0; c < 32; c++) {
        __nv_bfloat16 hb = __float2bfloat16(v[c]);
        float rest = v[c] - __bfloat162float(hb);
        __nv_bfloat16 lb = __float2bfloat16(rest);
        unsigned short hu, lu; memcpy(&hu, &hb, 2); memcpy(&lu, &lb, 2);
        vh[c] = hu; vl[c] = lu;
    }
}

// ======================= K4: main tile kernel (R7 shape + early W) =========
__device__ __forceinline__ void issue_chunk(uint32_t sb, uint32_t stage,
        const unsigned short* Ah, const unsigned short* Al,
        const unsigned short* Bh, const unsigned short* Bl,
        int chunk, int tid) {
    const unsigned short* gp[4] = {Ah, Al, Bh, Bl};
#pragma unroll
    for (int t = 0; t < 4; t++) {
#pragma unroll
        for (int q = 0; q < 2; q++) {
            int idx = q * 512 + tid;
            int row = idx >> 3, c16 = idx & 7;
            const unsigned short* src = gp[t] + row * 256 + chunk * 64 + c16 * 8;
            uint32_t dst = sb + stage + t * 16384 + row * 128 + ((c16 ^ (row & 7)) << 4);
            CP16(dst, src);
        }
    }
}

// Gram: 3-product accumulation over 4 ksteps of 16.
__device__ __forceinline__ void do_mma(uint32_t aH, uint32_t aL, uint32_t bH, uint32_t bL,
                                       int wm, int wn, int lane, float acc[2][4][4]) {
    int r16 = lane & 15;
    int cuA = lane >> 4;
    int cuB = (lane >> 3) & 1;
    int jrow = (lane >> 4) * 8;
#pragma unroll
    for (int ks = 0; ks < 4; ks++) {
        uint32_t ah[2][4], al[2][4], bh[2][4], bl[2][4];
#pragma unroll
        for (int i = 0; i < 2; i++) {
            int row = wm * 32 + i * 16 + r16;
            uint32_t ro = (uint32_t)(row * 128 + (((ks * 2 + cuA) ^ (row & 7)) << 4));
            ldsm4(ah[i], aH + ro);
            ldsm4(al[i], aL + ro);
        }
#pragma unroll
        for (int p = 0; p < 2; p++) {
            int row = wn * 32 + p * 16 + jrow + (lane & 7);
            uint32_t ro = (uint32_t)(row * 128 + (((ks * 2 + cuB) ^ (row & 7)) << 4));
            ldsm4(bh[p], bH + ro);
            ldsm4(bl[p], bL + ro);
        }
#pragma unroll
        for (int i = 0; i < 2; i++)
#pragma unroll
            for (int j = 0; j < 4; j++) {
                const uint32_t* fh = &bh[j >> 1][(j & 1) * 2];
                const uint32_t* fl = &bl[j >> 1][(j & 1) * 2];
                mma16816(acc[i][j], ah[i], fh);
                mma16816(acc[i][j], ah[i], fl);
                mma16816(acc[i][j], al[i], fh);
            }
    }
}

// V (packed hi segs 0-3, lo segs 4-7): 3-product over 2 ksteps of 16.
__device__ __forceinline__ void do_mma_v(uint32_t vA, uint32_t vB,
                                         int wm, int wn, int lane, float acc[2][4][4]) {
    int r16 = lane & 15;
    int cuA = lane >> 4;
    int cuB = (lane >> 3) & 1;
    int jrow = (lane >> 4) * 8;
#pragma unroll
    for (int ks = 0; ks < 2; ks++) {
        uint32_t ah[2][4], al[2][4], bh[2][4], bl[2][4];
#pragma unroll
        for (int i = 0; i < 2; i++) {
            int row = wm * 32 + i * 16 + r16;
            uint32_t roh = (uint32_t)(row * 128 + (((ks * 2 + cuA) ^ (row & 7)) << 4));
            uint32_t rol = (uint32_t)(row * 128 + (((ks * 2 + cuA + 4) ^ (row & 7)) << 4));
            ldsm4(ah[i], vA + roh);
            ldsm4(al[i], vA + rol);
        }
#pragma unroll
        for (int p = 0; p < 2; p++) {
            int row = wn * 32 + p * 16 + jrow + (lane & 7);
            uint32_t roh = (uint32_t)(row * 128 + (((ks * 2 + cuB) ^ (row & 7)) << 4));
            uint32_t rol = (uint32_t)(row * 128 + (((ks * 2 + cuB + 4) ^ (row & 7)) << 4));
            ldsm4(bh[p], vB + roh);
            ldsm4(bl[p], vB + rol);
        }
#pragma unroll
        for (int i = 0; i < 2; i++)
#pragma unroll
            for (int j = 0; j < 4; j++) {
                const uint32_t* fh = &bh[j >> 1][(j & 1) * 2];
                const uint32_t* fl = &bl[j >> 1][(j & 1) * 2];
                mma16816(acc[i][j], ah[i], fh);
                mma16816(acc[i][j], ah[i], fl);
                mma16816(acc[i][j], al[i], fh);
            }
    }
}

__global__ void __launch_bounds__(512, 1) k_main() {
    extern __shared__ __align__(1024) char smem[];
    uint32_t sb = smem_u32(smem);
    int tid = threadIdx.x, wid = tid >> 5, lane = tid & 31;
    int wm = wid & 3, wn = wid >> 2;

    int bid = blockIdx.x, ti = 0, rem = bid;
    while (rem >= TILES - ti) { rem -= TILES - ti; ti++; }
    int tj = ti + rem;
    int rA = ti * 128, rB = tj * 128;

    float* ssqa = (float*)(smem + SM_SQA);
    float* ssqb = (float*)(smem + SM_SQB);
    float* sred = (float*)(smem + SM_RED);
    if (tid < 128) ssqa[tid] = g_sq[rA + tid];
    else if (tid < 256) ssqb[tid - 128] = g_sq[rB + tid - 128];

    const unsigned short* Ah = g_Xh + (size_t)rA * 256;
    const unsigned short* Al = g_Xl + (size_t)rA * 256;
    const unsigned short* Bh = g_Xh + (size_t)rB * 256;
    const unsigned short* Bl = g_Xl + (size_t)rB * 256;

    // group0: V (packed) + chunk0 -> s0
    {
        int row = tid >> 2, c16 = tid & 3;
        const unsigned short* vah = g_Vh + (size_t)rA * 32;
        const unsigned short* val = g_Vl + (size_t)rA * 32;
        const unsigned short* vbh = g_Vh + (size_t)rB * 32;
        const unsigned short* vbl = g_Vl + (size_t)rB * 32;
        uint32_t rb = sb + row * 128;
        CP16(rb + SM_VA + ((c16 ^ (row & 7)) << 4),        vah + row * 32 + c16 * 8);
        CP16(rb + SM_VA + (((c16 + 4) ^ (row & 7)) << 4),  val + row * 32 + c16 * 8);
        CP16(rb + SM_VB + ((c16 ^ (row & 7)) << 4),        vbh + row * 32 + c16 * 8);
        CP16(rb + SM_VB + (((c16 + 4) ^ (row & 7)) << 4),  vbl + row * 32 + c16 * 8);
        issue_chunk(sb, SM_S0, Ah, Al, Bh, Bl, 0, tid);
        CP_COMMIT();
    }
    issue_chunk(sb, SM_S1, Ah, Al, Bh, Bl, 1, tid);
    CP_COMMIT();

    float acc[2][4][4], wacc[2][4][4];
#pragma unroll
    for (int i = 0; i < 2; i++)
#pragma unroll
        for (int j = 0; j < 4; j++)
#pragma unroll
            for (int r = 0; r < 4; r++) { acc[i][j][r] = 0.f; wacc[i][j][r] = 0.f; }

    const uint32_t stg[3] = {sb + SM_S0, sb + SM_S1, sb + SM_S2};
#pragma unroll 1
    for (int c = 0; c < 4; c++) {
        if (c < 3) { CP_WAIT1(); } else { CP_WAIT0(); }
        __syncthreads();
        if (c < 2) {
            issue_chunk(sb, (c == 0) ? SM_S2 : SM_S0, Ah, Al, Bh, Bl, c + 2, tid);
            CP_COMMIT();
        }
        if (c == 0) {
            // V arrived with group0 — knock out W early, off the critical tail
            do_mma_v(sb + SM_VA, sb + SM_VB, wm, wn, lane, wacc);
        }
        uint32_t st = stg[c % 3];
        do_mma(st, st + 16384, st + 32768, st + 49152, wm, wn, lane, acc);
    }

    // ---- epilogue ----
    float sqa_r[4], sqb_c[8];
#pragma unroll
    for (int i = 0; i < 2; i++)
#pragma unroll
        for (int rh = 0; rh < 2; rh++)
            sqa_r[i * 2 + rh] = ssqa[wm * 32 + i * 16 + (lane >> 2) + rh * 8];
#pragma unroll
    for (int j = 0; j < 4; j++)
#pragma unroll
        for (int cc2 = 0; cc2 < 2; cc2++)
            sqb_c[j * 2 + cc2] = ssqb[wn * 32 + j * 8 + (lane & 3) * 2 + cc2];

    float c0 = g_c0;
    int chain = g_chain;
    float cf0 = 0, cf1 = 0, cf2 = 0, cf3 = 0, cf4 = 0;
    if (!chain) { cf0 = g_coef[0]; cf1 = g_coef[1]; cf2 = g_coef[2]; cf3 = g_coef[3]; cf4 = g_coef[4]; }

    float part = 0.f;
#pragma unroll
    for (int i = 0; i < 2; i++)
#pragma unroll
        for (int j = 0; j < 4; j++)
#pragma unroll
            for (int r = 0; r < 4; r++) {
                float l2 = fmaf(-2.0f, acc[i][j][r], sqa_r[i * 2 + (r >> 1)] + sqb_c[j * 2 + (r & 1)]);
                l2 = fmaxf(l2, 0.0f);
                float ks;
                if (chain) {
                    float x  = ex2f(-l2 * c0);
                    float x2 = x * x, x4 = x2 * x2, x8 = x4 * x4;
                    ks = x + x2 + x4 + x8 + x8 * x8;
                } else {
                    ks = ex2f(-l2 * cf0) + ex2f(-l2 * cf1) + ex2f(-l2 * cf2)
                       + ex2f(-l2 * cf3) + ex2f(-l2 * cf4);
                }
                part = fmaf(ks, wacc[i][j][r], part);
            }
    if (ti != tj) part *= 2.0f;

#pragma unroll
    for (int off = 16; off; off >>= 1) part += __shfl_xor_sync(0xffffffffu, part, off);
    if (lane == 0) sred[wid] = part;
    __syncthreads();
    if (tid == 0) {
        float s = 0.f;
#pragma unroll
        for (int w = 0; w < 16; w++) s += sred[w];
        atomicAdd(&g_loss, (double)s);
    }
}

__global__ void k_out(float* out) {
    out[0] = (float)(g_loss * (double)g_inv_nidx);
}

// ======================= launch =======================
extern "C" void kernel_launch(void* const* d_in, const int* in_sizes, int n_in,
                              void* d_out, int out_size) {
    const float* src = (const float*)d_in[0];
    const float* tgt = (const float*)d_in[1];
    const int*   sl  = (const int*)d_in[2];
    const float* tl  = (const float*)d_in[3];
    float* out = (float*)d_out;

    cudaFuncSetAttribute(k_main, cudaFuncAttributeMaxDynamicSharedMemorySize, SMEM_TOTAL);

    k_prep<<<1024, 256>>>(src, tgt, sl, tl);
    k_finalize<<<1, 256>>>();
    k_buildV<<<32, 256>>>(sl, tl);
    k_main<<<NTILEPAIRS, 512, SMEM_TOTAL>>>();
    k_out<<<1, 1>>>(out);
}

// round 10
// speedup vs baseline: 4.4150x; 1.2106x over previous
#include <cuda_runtime.h>
#include <cuda_bf16.h>
#include <cstdint>
#include <cstring>
#include <math.h>

#define NB 4096
#define NT 8192
#define DD 256
#define CC 31
#define TILES 64
#define NTILEPAIRS 2080

// ======================= device scratch =======================
__device__ float  g_sq[NT];
__device__ float  g_colpart[1024][DD];
__device__ float  g_colpart2[64][DD];
__device__ float  g_tpart[512][32];
__device__ int    g_scnt_part[512][32];
__device__ int    g_tpres_part[512][32];
__device__ float  g_tpart2[32][32];
__device__ int    g_scnt2[32][32];
__device__ int    g_tpres2[32][32];
__device__ float  g_sScale[32];
__device__ float  g_tScale[32];
__device__ float  g_coef[5];
__device__ float  g_c0;
__device__ int    g_chain;
__device__ float  g_inv_nidx;
__device__ double g_loss;

__device__ __align__(16) unsigned short g_Xh[NT * DD];
__device__ __align__(16) unsigned short g_Xl[NT * DD];
__device__ __align__(16) unsigned short g_Vh[NT * 32];
__device__ __align__(16) unsigned short g_Vl[NT * 32];

// ======================= helpers =======================
__device__ __forceinline__ float ex2f(float x) {
    float y; asm("ex2.approx.ftz.f32 %0, %1;" : "=f"(y) : "f"(x)); return y;
}
__device__ __forceinline__ uint32_t smem_u32(const void* p) {
    uint32_t a;
    asm("{ .reg .u64 t; cvta.to.shared.u64 t, %1; cvt.u32.u64 %0, t; }" : "=r"(a) : "l"(p));
    return a;
}
#define CP16(dst, src) \
    asm volatile("cp.async.cg.shared.global [%0], [%1], 16;" :: "r"(dst), "l"(src))
#define CP_COMMIT() asm volatile("cp.async.commit_group;" ::: "memory")
#define CP_WAIT1()  asm volatile("cp.async.wait_group 1;" ::: "memory")
#define CP_WAIT0()  asm volatile("cp.async.wait_group 0;" ::: "memory")

__device__ __forceinline__ void ldsm4(uint32_t r[4], uint32_t addr) {
    asm volatile("ldmatrix.sync.aligned.m8n8.x4.shared.b16 {%0,%1,%2,%3}, [%4];"
        : "=r"(r[0]), "=r"(r[1]), "=r"(r[2]), "=r"(r[3]) : "r"(addr));
}
__device__ __forceinline__ void mma16816(float d[4], const uint32_t a[4], const uint32_t b[2]) {
    asm volatile("mma.sync.aligned.m16n8k16.row.col.f32.bf16.bf16.f32 "
        "{%0,%1,%2,%3}, {%4,%5,%6,%7}, {%8,%9}, {%0,%1,%2,%3};"
        : "+f"(d[0]), "+f"(d[1]), "+f"(d[2]), "+f"(d[3])
        : "r"(a[0]), "r"(a[1]), "r"(a[2]), "r"(a[3]), "r"(b[0]), "r"(b[1]));
}

// ======================= smem layout (k_main) =======================
#define SM_VA   0
#define SM_VB   16384
#define SM_S0   32768
#define SM_S1   (32768 + 65536)
#define SM_S2   (32768 + 2 * 65536)
#define SM_SQA  229376
#define SM_SQB  229888
#define SM_RED  230400
#define SMEM_TOTAL 230464

// ======================= K1: fused prepass (1024 CTAs) =======================
__global__ void __launch_bounds__(256) k_prep(
        const float* __restrict__ src, const float* __restrict__ tgt,
        const int* __restrict__ s_label, const float* __restrict__ t_label) {
    __shared__ float scol[8][DD];
    __shared__ float stsum[8][32];
    __shared__ int   sharg[8];
    __shared__ int   scnt[32];
    int b = blockIdx.x, t = threadIdx.x, w = t >> 5, l = t & 31;
    int row = b * 8 + w;
    const float* rp = (row < NB) ? src + (size_t)row * DD : tgt + (size_t)(row - NB) * DD;

    float4 x0 = *(const float4*)(rp + l * 8);
    float4 x1 = *(const float4*)(rp + l * 8 + 4);
    float xs[8] = {x0.x, x0.y, x0.z, x0.w, x1.x, x1.y, x1.z, x1.w};

    float s = 0.f;
#pragma unroll
    for (int k = 0; k < 8; k++) s = fmaf(xs[k], xs[k], s);
#pragma unroll
    for (int off = 16; off; off >>= 1) s += __shfl_xor_sync(0xffffffffu, s, off);
    if (l == 0) g_sq[row] = s;

    unsigned short h[8], lo[8];
#pragma unroll
    for (int k = 0; k < 8; k++) {
        __nv_bfloat16 hb = __float2bfloat16(xs[k]);
        float rest = xs[k] - __bfloat162float(hb);
        __nv_bfloat16 lb = __float2bfloat16(rest);
        memcpy(&h[k], &hb, 2); memcpy(&lo[k], &lb, 2);
    }
    size_t e = (size_t)row * DD + l * 8;
    *(uint2*)(g_Xh + e)     = make_uint2((uint32_t)h[0] | ((uint32_t)h[1] << 16),
                                         (uint32_t)h[2] | ((uint32_t)h[3] << 16));
    *(uint2*)(g_Xh + e + 4) = make_uint2((uint32_t)h[4] | ((uint32_t)h[5] << 16),
                                         (uint32_t)h[6] | ((uint32_t)h[7] << 16));
    *(uint2*)(g_Xl + e)     = make_uint2((uint32_t)lo[0] | ((uint32_t)lo[1] << 16),
                                         (uint32_t)lo[2] | ((uint32_t)lo[3] << 16));
    *(uint2*)(g_Xl + e + 4) = make_uint2((uint32_t)lo[4] | ((uint32_t)lo[5] << 16),
                                         (uint32_t)lo[6] | ((uint32_t)lo[7] << 16));

#pragma unroll
    for (int k = 0; k < 8; k++) scol[w][l * 8 + k] = xs[k];
    __syncthreads();
    {
        float m = 0.f;
#pragma unroll
        for (int ww = 0; ww < 8; ww++) m += scol[ww][t];
        g_colpart[b][t] = m;
    }

    if (b < 512) {
        if (t < 32) scnt[t] = 0;
        __syncthreads();
        if (l == 0) {
            int lbl = s_label[row];
            if ((unsigned)lbl < CC) atomicAdd(&scnt[lbl], 1);
        }
        __syncthreads();
        if (t < 32) g_scnt_part[b][t] = scnt[t];
    } else {
        int tb = b - 512;
        const float* tr = t_label + (size_t)(row - NB) * CC;
        float v = (l < CC) ? tr[l] : -1e30f;
        stsum[w][l] = (l < CC) ? v : 0.f;
        float bv = v; int bi = l;
#pragma unroll
        for (int off = 16; off; off >>= 1) {
            float ov = __shfl_xor_sync(0xffffffffu, bv, off);
            int   oi = __shfl_xor_sync(0xffffffffu, bi, off);
            if (ov > bv || (ov == bv && oi < bi)) { bv = ov; bi = oi; }
        }
        if (l == 0) sharg[w] = bi;
        __syncthreads();
        if (t < 32) {
            float tc = 0.f; int pres = 0;
#pragma unroll
            for (int ww = 0; ww < 8; ww++) {
                tc += stsum[ww][t];
                pres |= (sharg[ww] == t);
            }
            g_tpart[tb][t] = tc;
            g_tpres_part[tb][t] = pres;
        }
    }
}

// ======================= K2: parallel partial fold (96 CTAs) =======================
__global__ void __launch_bounds__(256) k_reduce() {
    int b = blockIdx.x, t = threadIdx.x;
    if (b < 64) {
        float m = 0.f;
#pragma unroll
        for (int r = 0; r < 16; r++) m += g_colpart[b * 16 + r][t];
        g_colpart2[b][t] = m;
    } else {
        int rb = b - 64;                 // 0..31
        if (t < 32) {
            int cnt = 0, pres = 0;
            float tc = 0.f;
#pragma unroll
            for (int r = 0; r < 16; r++) {
                int blk = rb * 16 + r;
                cnt  += g_scnt_part[blk][t];
                pres |= g_tpres_part[blk][t];
                tc   += g_tpart[blk][t];
            }
            g_scnt2[rb][t] = cnt;
            g_tpres2[rb][t] = pres;
            g_tpart2[rb][t] = tc;
        }
    }
}

// ======================= K3: finalize scalars (cheap now) =======================
__global__ void k_finalize() {
    __shared__ double red[256];
    __shared__ double sMSQ;
    int t = threadIdx.x;

    float m = 0.f;
#pragma unroll
    for (int b = 0; b < 64; b++) m += g_colpart2[b][t];
    red[t] = (double)m * (double)m;
    __syncthreads();
    for (int off = 128; off; off >>= 1) { if (t < off) red[t] += red[t + off]; __syncthreads(); }
    if (t == 0) sMSQ = red[0];
    __syncthreads();

    double s1 = 0.0;
    for (int r = t; r < NT; r += 256) s1 += (double)g_sq[r];
    red[t] = s1;
    __syncthreads();
    for (int off = 128; off; off >>= 1) { if (t < off) red[t] += red[t + off]; __syncthreads(); }

    if (t < 32) {
        int cnt = 0, pres = 0;
        float tc = 0.f;
#pragma unroll
        for (int b = 0; b < 32; b++) {
            cnt  += g_scnt2[b][t];
            pres |= g_tpres2[b][t];
            tc   += g_tpart2[b][t];
        }
        int msk = (t < CC) && (cnt > 0) && pres;
        unsigned bal = __ballot_sync(0xffffffffu, msk);
        int nidx = __popc(bal);
        if (nidx < 1) nidx = 1;
        g_sScale[t] = msk ? 1.0f / (float)cnt : 0.f;
        float tdiv = (tc == 0.f) ? 100.f : tc;
        g_tScale[t] = msk ? 1.0f / tdiv : 0.f;
        if (t == 0) g_inv_nidx = 1.0f / (float)nidx;
    }

    if (t == 0) {
        g_loss = 0.0;
        double S1 = red[0], MSQ = sMSQ;
        double sum_l2 = 2.0 * (double)NT * S1 - 2.0 * MSQ;
        double bw = sum_l2 / ((double)NT * (double)NT - (double)NT);
        if (bw < 1e-6) bw = 1e-6;
        bw *= 0.25;
        g_chain = (bw >= 1e-6) ? 1 : 0;
        const double L2E = 1.4426950408889634;
        for (int i = 0; i < 5; i++) {
            double den = bw * (double)(1 << i);
            if (den < 1e-6) den = 1e-6;
            g_coef[i] = (float)(L2E / den);
        }
        g_c0 = g_coef[4];
    }
}

// ======================= K4: build signed weight vectors =======================
__global__ void k_buildV(const int* __restrict__ s_label, const float* __restrict__ t_label) {
    int i = blockIdx.x * 256 + threadIdx.x;
    float v[32];
    if (i < NB) {
#pragma unroll
        for (int c = 0; c < 32; c++) v[c] = 0.f;
        int lbl = s_label[i];
        if ((unsigned)lbl < CC) v[lbl] = g_sScale[lbl];
    } else {
        const float* tr = t_label + (size_t)(i - NB) * CC;
#pragma unroll
        for (int c = 0; c < CC; c++) v[c] = -tr[c] * g_tScale[c];
        v[31] = 0.f;
    }
    unsigned short* vh = g_Vh + (size_t)i * 32;
    unsigned short* vl = g_Vl + (size_t)i * 32;
#pragma unroll
    for (int c = 0; c < 32; c++) {
        __nv_bfloat16 hb = __float2bfloat16(v[c]);
        float rest = v[c] - __bfloat162float(hb);
        __nv_bfloat16 lb = __float2bfloat16(rest);
        unsigned short hu, lu; memcpy(&hu, &hb, 2); memcpy(&lu, &lb, 2);
        vh[c] = hu; vl[c] = lu;
    }
}

// ======================= K5: main tile kernel (unchanged from R9) =========
__device__ __forceinline__ void issue_chunk(uint32_t sb, uint32_t stage,
        const unsigned short* Ah, const unsigned short* Al,
        const unsigned short* Bh, const unsigned short* Bl,
        int chunk, int tid) {
    const unsigned short* gp[4] = {Ah, Al, Bh, Bl};
#pragma unroll
    for (int t = 0; t < 4; t++) {
#pragma unroll
        for (int q = 0; q < 2; q++) {
            int idx = q * 512 + tid;
            int row = idx >> 3, c16 = idx & 7;
            const unsigned short* src = gp[t] + row * 256 + chunk * 64 + c16 * 8;
            uint32_t dst = sb + stage + t * 16384 + row * 128 + ((c16 ^ (row & 7)) << 4);
            CP16(dst, src);
        }
    }
}

__device__ __forceinline__ void do_mma(uint32_t aH, uint32_t aL, uint32_t bH, uint32_t bL,
                                       int wm, int wn, int lane, float acc[2][4][4]) {
    int r16 = lane & 15;
    int cuA = lane >> 4;
    int cuB = (lane >> 3) & 1;
    int jrow = (lane >> 4) * 8;
#pragma unroll
    for (int ks = 0; ks < 4; ks++) {
        uint32_t ah[2][4], al[2][4], bh[2][4], bl[2][4];
#pragma unroll
        for (int i = 0; i < 2; i++) {
            int row = wm * 32 + i * 16 + r16;
            uint32_t ro = (uint32_t)(row * 128 + (((ks * 2 + cuA) ^ (row & 7)) << 4));
            ldsm4(ah[i], aH + ro);
            ldsm4(al[i], aL + ro);
        }
#pragma unroll
        for (int p = 0; p < 2; p++) {
            int row = wn * 32 + p * 16 + jrow + (lane & 7);
            uint32_t ro = (uint32_t)(row * 128 + (((ks * 2 + cuB) ^ (row & 7)) << 4));
            ldsm4(bh[p], bH + ro);
            ldsm4(bl[p], bL + ro);
        }
#pragma unroll
        for (int i = 0; i < 2; i++)
#pragma unroll
            for (int j = 0; j < 4; j++) {
                const uint32_t* fh = &bh[j >> 1][(j & 1) * 2];
                const uint32_t* fl = &bl[j >> 1][(j & 1) * 2];
                mma16816(acc[i][j], ah[i], fh);
                mma16816(acc[i][j], ah[i], fl);
                mma16816(acc[i][j], al[i], fh);
            }
    }
}

__device__ __forceinline__ void do_mma_v(uint32_t vA, uint32_t vB,
                                         int wm, int wn, int lane, float acc[2][4][4]) {
    int r16 = lane & 15;
    int cuA = lane >> 4;
    int cuB = (lane >> 3) & 1;
    int jrow = (lane >> 4) * 8;
#pragma unroll
    for (int ks = 0; ks < 2; ks++) {
        uint32_t ah[2][4], al[2][4], bh[2][4], bl[2][4];
#pragma unroll
        for (int i = 0; i < 2; i++) {
            int row = wm * 32 + i * 16 + r16;
            uint32_t roh = (uint32_t)(row * 128 + (((ks * 2 + cuA) ^ (row & 7)) << 4));
            uint32_t rol = (uint32_t)(row * 128 + (((ks * 2 + cuA + 4) ^ (row & 7)) << 4));
            ldsm4(ah[i], vA + roh);
            ldsm4(al[i], vA + rol);
        }
#pragma unroll
        for (int p = 0; p < 2; p++) {
            int row = wn * 32 + p * 16 + jrow + (lane & 7);
            uint32_t roh = (uint32_t)(row * 128 + (((ks * 2 + cuB) ^ (row & 7)) << 4));
            uint32_t rol = (uint32_t)(row * 128 + (((ks * 2 + cuB + 4) ^ (row & 7)) << 4));
            ldsm4(bh[p], vB + roh);
            ldsm4(bl[p], vB + rol);
        }
#pragma unroll
        for (int i = 0; i < 2; i++)
#pragma unroll
            for (int j = 0; j < 4; j++) {
                const uint32_t* fh = &bh[j >> 1][(j & 1) * 2];
                const uint32_t* fl = &bl[j >> 1][(j & 1) * 2];
                mma16816(acc[i][j], ah[i], fh);
                mma16816(acc[i][j], ah[i], fl);
                mma16816(acc[i][j], al[i], fh);
            }
    }
}

__global__ void __launch_bounds__(512, 1) k_main() {
    extern __shared__ __align__(1024) char smem[];
    uint32_t sb = smem_u32(smem);
    int tid = threadIdx.x, wid = tid >> 5, lane = tid & 31;
    int wm = wid & 3, wn = wid >> 2;

    int bid = blockIdx.x, ti = 0, rem = bid;
    while (rem >= TILES - ti) { rem -= TILES - ti; ti++; }
    int tj = ti + rem;
    int rA = ti * 128, rB = tj * 128;

    float* ssqa = (float*)(smem + SM_SQA);
    float* ssqb = (float*)(smem + SM_SQB);
    float* sred = (float*)(smem + SM_RED);
    if (tid < 128) ssqa[tid] = g_sq[rA + tid];
    else if (tid < 256) ssqb[tid - 128] = g_sq[rB + tid - 128];

    const unsigned short* Ah = g_Xh + (size_t)rA * 256;
    const unsigned short* Al = g_Xl + (size_t)rA * 256;
    const unsigned short* Bh = g_Xh + (size_t)rB * 256;
    const unsigned short* Bl = g_Xl + (size_t)rB * 256;

    {
        int row = tid >> 2, c16 = tid & 3;
        const unsigned short* vah = g_Vh + (size_t)rA * 32;
        const unsigned short* val = g_Vl + (size_t)rA * 32;
        const unsigned short* vbh = g_Vh + (size_t)rB * 32;
        const unsigned short* vbl = g_Vl + (size_t)rB * 32;
        uint32_t rb = sb + row * 128;
        CP16(rb + SM_VA + ((c16 ^ (row & 7)) << 4),        vah + row * 32 + c16 * 8);
        CP16(rb + SM_VA + (((c16 + 4) ^ (row & 7)) << 4),  val + row * 32 + c16 * 8);
        CP16(rb + SM_VB + ((c16 ^ (row & 7)) << 4),        vbh + row * 32 + c16 * 8);
        CP16(rb + SM_VB + (((c16 + 4) ^ (row & 7)) << 4),  vbl + row * 32 + c16 * 8);
        issue_chunk(sb, SM_S0, Ah, Al, Bh, Bl, 0, tid);
        CP_COMMIT();
    }
    issue_chunk(sb, SM_S1, Ah, Al, Bh, Bl, 1, tid);
    CP_COMMIT();

    float acc[2][4][4], wacc[2][4][4];
#pragma unroll
    for (int i = 0; i < 2; i++)
#pragma unroll
        for (int j = 0; j < 4; j++)
#pragma unroll
            for (int r = 0; r < 4; r++) { acc[i][j][r] = 0.f; wacc[i][j][r] = 0.f; }

    const uint32_t stg[3] = {sb + SM_S0, sb + SM_S1, sb + SM_S2};
#pragma unroll 1
    for (int c = 0; c < 4; c++) {
        if (c < 3) { CP_WAIT1(); } else { CP_WAIT0(); }
        __syncthreads();
        if (c < 2) {
            issue_chunk(sb, (c == 0) ? SM_S2 : SM_S0, Ah, Al, Bh, Bl, c + 2, tid);
            CP_COMMIT();
        }
        if (c == 0) {
            do_mma_v(sb + SM_VA, sb + SM_VB, wm, wn, lane, wacc);
        }
        uint32_t st = stg[c % 3];
        do_mma(st, st + 16384, st + 32768, st + 49152, wm, wn, lane, acc);
    }

    // ---- epilogue ----
    float sqa_r[4], sqb_c[8];
#pragma unroll
    for (int i = 0; i < 2; i++)
#pragma unroll
        for (int rh = 0; rh < 2; rh++)
            sqa_r[i * 2 + rh] = ssqa[wm * 32 + i * 16 + (lane >> 2) + rh * 8];
#pragma unroll
    for (int j = 0; j < 4; j++)
#pragma unroll
        for (int cc2 = 0; cc2 < 2; cc2++)
            sqb_c[j * 2 + cc2] = ssqb[wn * 32 + j * 8 + (lane & 3) * 2 + cc2];

    float c0 = g_c0;
    int chain = g_chain;
    float cf0 = 0, cf1 = 0, cf2 = 0, cf3 = 0, cf4 = 0;
    if (!chain) { cf0 = g_coef[0]; cf1 = g_coef[1]; cf2 = g_coef[2]; cf3 = g_coef[3]; cf4 = g_coef[4]; }

    float part = 0.f;
#pragma unroll
    for (int i = 0; i < 2; i++)
#pragma unroll
        for (int j = 0; j < 4; j++)
#pragma unroll
            for (int r = 0; r < 4; r++) {
                float l2 = fmaf(-2.0f, acc[i][j][r], sqa_r[i * 2 + (r >> 1)] + sqb_c[j * 2 + (r & 1)]);
                l2 = fmaxf(l2, 0.0f);
                float ks;
                if (chain) {
                    float x  = ex2f(-l2 * c0);
                    float x2 = x * x, x4 = x2 * x2, x8 = x4 * x4;
                    ks = x + x2 + x4 + x8 + x8 * x8;
                } else {
                    ks = ex2f(-l2 * cf0) + ex2f(-l2 * cf1) + ex2f(-l2 * cf2)
                       + ex2f(-l2 * cf3) + ex2f(-l2 * cf4);
                }
                part = fmaf(ks, wacc[i][j][r], part);
            }
    if (ti != tj) part *= 2.0f;

#pragma unroll
    for (int off = 16; off; off >>= 1) part += __shfl_xor_sync(0xffffffffu, part, off);
    if (lane == 0) sred[wid] = part;
    __syncthreads();
    if (tid == 0) {
        float s = 0.f;
#pragma unroll
        for (int w = 0; w < 16; w++) s += sred[w];
        atomicAdd(&g_loss, (double)s);
    }
}

__global__ void k_out(float* out) {
    out[0] = (float)(g_loss * (double)g_inv_nidx);
}

// ======================= launch =======================
extern "C" void kernel_launch(void* const* d_in, const int* in_sizes, int n_in,
                              void* d_out, int out_size) {
    const float* src = (const float*)d_in[0];
    const float* tgt = (const float*)d_in[1];
    const int*   sl  = (const int*)d_in[2];
    const float* tl  = (const float*)d_in[3];
    float* out = (float*)d_out;

    cudaFuncSetAttribute(k_main, cudaFuncAttributeMaxDynamicSharedMemorySize, SMEM_TOTAL);

    k_prep<<<1024, 256>>>(src, tgt, sl, tl);
    k_reduce<<<96, 256>>>();
    k_finalize<<<1, 256>>>();
    k_buildV<<<32, 256>>>(sl, tl);
    k_main<<<NTILEPAIRS, 512, SMEM_TOTAL>>>();
    k_out<<<1, 1>>>(out);
}

// round 11
// speedup vs baseline: 4.5178x; 1.0233x over previous
#include <cuda_runtime.h>
#include <cuda_bf16.h>
#include <cstdint>
#include <cstring>
#include <math.h>

#define NB 4096
#define NT 8192
#define DD 256
#define CC 31
#define TILES 64
#define NTILEPAIRS 2080
#define NSM 148

// ======================= device scratch =======================
__device__ float  g_sq[NT];
__device__ float  g_colpart[1024][DD];
__device__ float  g_colpart2[64][DD];
__device__ float  g_tpart[512][32];
__device__ int    g_scnt_part[512][32];
__device__ int    g_tpres_part[512][32];
__device__ float  g_tpart2[32][32];
__device__ int    g_scnt2[32][32];
__device__ int    g_tpres2[32][32];
__device__ float  g_sScale[32];
__device__ float  g_tScale[32];
__device__ float  g_coef[5];
__device__ float  g_c0;
__device__ int    g_chain;
__device__ float  g_inv_nidx;
__device__ double g_loss;

__device__ __align__(16) unsigned short g_Xh[NT * DD];
__device__ __align__(16) unsigned short g_Xl[NT * DD];
__device__ __align__(16) unsigned short g_Vh[NT * 32];
__device__ __align__(16) unsigned short g_Vl[NT * 32];

// ======================= helpers =======================
__device__ __forceinline__ float ex2f(float x) {
    float y; asm("ex2.approx.ftz.f32 %0, %1;" : "=f"(y) : "f"(x)); return y;
}
__device__ __forceinline__ uint32_t smem_u32(const void* p) {
    uint32_t a;
    asm("{ .reg .u64 t; cvta.to.shared.u64 t, %1; cvt.u32.u64 %0, t; }" : "=r"(a) : "l"(p));
    return a;
}
#define CP16(dst, src) \
    asm volatile("cp.async.cg.shared.global [%0], [%1], 16;" :: "r"(dst), "l"(src))
#define CP_COMMIT() asm volatile("cp.async.commit_group;" ::: "memory")
#define CP_WAIT1()  asm volatile("cp.async.wait_group 1;" ::: "memory")
#define CP_WAIT0()  asm volatile("cp.async.wait_group 0;" ::: "memory")

__device__ __forceinline__ void ldsm4(uint32_t r[4], uint32_t addr) {
    asm volatile("ldmatrix.sync.aligned.m8n8.x4.shared.b16 {%0,%1,%2,%3}, [%4];"
        : "=r"(r[0]), "=r"(r[1]), "=r"(r[2]), "=r"(r[3]) : "r"(addr));
}
__device__ __forceinline__ void mma16816(float d[4], const uint32_t a[4], const uint32_t b[2]) {
    asm volatile("mma.sync.aligned.m16n8k16.row.col.f32.bf16.bf16.f32 "
        "{%0,%1,%2,%3}, {%4,%5,%6,%7}, {%8,%9}, {%0,%1,%2,%3};"
        : "+f"(d[0]), "+f"(d[1]), "+f"(d[2]), "+f"(d[3])
        : "r"(a[0]), "r"(a[1]), "r"(a[2]), "r"(a[3]), "r"(b[0]), "r"(b[1]));
}

// ======================= smem layout (k_main) =======================
#define SM_VA   0
#define SM_VB   16384
#define SM_S    32768
#define STAGE   65536
#define SM_RED  (32768 + 3 * STAGE)       // 229376
#define SMEM_TOTAL (SM_RED + 64)          // 229440 < 232448

// ======================= K1: fused prepass (1024 CTAs) =======================
__global__ void __launch_bounds__(256) k_prep(
        const float* __restrict__ src, const float* __restrict__ tgt,
        const int* __restrict__ s_label, const float* __restrict__ t_label) {
    __shared__ float scol[8][DD];
    __shared__ float stsum[8][32];
    __shared__ int   sharg[8];
    __shared__ int   scnt[32];
    int b = blockIdx.x, t = threadIdx.x, w = t >> 5, l = t & 31;
    int row = b * 8 + w;
    const float* rp = (row < NB) ? src + (size_t)row * DD : tgt + (size_t)(row - NB) * DD;

    float4 x0 = *(const float4*)(rp + l * 8);
    float4 x1 = *(const float4*)(rp + l * 8 + 4);
    float xs[8] = {x0.x, x0.y, x0.z, x0.w, x1.x, x1.y, x1.z, x1.w};

    float s = 0.f;
#pragma unroll
    for (int k = 0; k < 8; k++) s = fmaf(xs[k], xs[k], s);
#pragma unroll
    for (int off = 16; off; off >>= 1) s += __shfl_xor_sync(0xffffffffu, s, off);
    if (l == 0) g_sq[row] = s;

    unsigned short h[8], lo[8];
#pragma unroll
    for (int k = 0; k < 8; k++) {
        __nv_bfloat16 hb = __float2bfloat16(xs[k]);
        float rest = xs[k] - __bfloat162float(hb);
        __nv_bfloat16 lb = __float2bfloat16(rest);
        memcpy(&h[k], &hb, 2); memcpy(&lo[k], &lb, 2);
    }
    size_t e = (size_t)row * DD + l * 8;
    *(uint2*)(g_Xh + e)     = make_uint2((uint32_t)h[0] | ((uint32_t)h[1] << 16),
                                         (uint32_t)h[2] | ((uint32_t)h[3] << 16));
    *(uint2*)(g_Xh + e + 4) = make_uint2((uint32_t)h[4] | ((uint32_t)h[5] << 16),
                                         (uint32_t)h[6] | ((uint32_t)h[7] << 16));
    *(uint2*)(g_Xl + e)     = make_uint2((uint32_t)lo[0] | ((uint32_t)lo[1] << 16),
                                         (uint32_t)lo[2] | ((uint32_t)lo[3] << 16));
    *(uint2*)(g_Xl + e + 4) = make_uint2((uint32_t)lo[4] | ((uint32_t)lo[5] << 16),
                                         (uint32_t)lo[6] | ((uint32_t)lo[7] << 16));

#pragma unroll
    for (int k = 0; k < 8; k++) scol[w][l * 8 + k] = xs[k];
    __syncthreads();
    {
        float m = 0.f;
#pragma unroll
        for (int ww = 0; ww < 8; ww++) m += scol[ww][t];
        g_colpart[b][t] = m;
    }

    if (b < 512) {
        if (t < 32) scnt[t] = 0;
        __syncthreads();
        if (l == 0) {
            int lbl = s_label[row];
            if ((unsigned)lbl < CC) atomicAdd(&scnt[lbl], 1);
        }
        __syncthreads();
        if (t < 32) g_scnt_part[b][t] = scnt[t];
    } else {
        int tb = b - 512;
        const float* tr = t_label + (size_t)(row - NB) * CC;
        float v = (l < CC) ? tr[l] : -1e30f;
        stsum[w][l] = (l < CC) ? v : 0.f;
        float bv = v; int bi = l;
#pragma unroll
        for (int off = 16; off; off >>= 1) {
            float ov = __shfl_xor_sync(0xffffffffu, bv, off);
            int   oi = __shfl_xor_sync(0xffffffffu, bi, off);
            if (ov > bv || (ov == bv && oi < bi)) { bv = ov; bi = oi; }
        }
        if (l == 0) sharg[w] = bi;
        __syncthreads();
        if (t < 32) {
            float tc = 0.f; int pres = 0;
#pragma unroll
            for (int ww = 0; ww < 8; ww++) {
                tc += stsum[ww][t];
                pres |= (sharg[ww] == t);
            }
            g_tpart[tb][t] = tc;
            g_tpres_part[tb][t] = pres;
        }
    }
}

// ======================= K2: parallel partial fold (96 CTAs) =======================
__global__ void __launch_bounds__(256) k_reduce() {
    int b = blockIdx.x, t = threadIdx.x;
    if (b < 64) {
        float m = 0.f;
#pragma unroll
        for (int r = 0; r < 16; r++) m += g_colpart[b * 16 + r][t];
        g_colpart2[b][t] = m;
    } else {
        int rb = b - 64;
        if (t < 32) {
            int cnt = 0, pres = 0;
            float tc = 0.f;
#pragma unroll
            for (int r = 0; r < 16; r++) {
                int blk = rb * 16 + r;
                cnt  += g_scnt_part[blk][t];
                pres |= g_tpres_part[blk][t];
                tc   += g_tpart[blk][t];
            }
            g_scnt2[rb][t] = cnt;
            g_tpres2[rb][t] = pres;
            g_tpart2[rb][t] = tc;
        }
    }
}

// ======================= K3: finalize scalars =======================
__global__ void k_finalize() {
    __shared__ double red[256];
    __shared__ double sMSQ;
    int t = threadIdx.x;

    float m = 0.f;
#pragma unroll
    for (int b = 0; b < 64; b++) m += g_colpart2[b][t];
    red[t] = (double)m * (double)m;
    __syncthreads();
    for (int off = 128; off; off >>= 1) { if (t < off) red[t] += red[t + off]; __syncthreads(); }
    if (t == 0) sMSQ = red[0];
    __syncthreads();

    double s1 = 0.0;
    for (int r = t; r < NT; r += 256) s1 += (double)g_sq[r];
    red[t] = s1;
    __syncthreads();
    for (int off = 128; off; off >>= 1) { if (t < off) red[t] += red[t + off]; __syncthreads(); }

    if (t < 32) {
        int cnt = 0, pres = 0;
        float tc = 0.f;
#pragma unroll
        for (int b = 0; b < 32; b++) {
            cnt  += g_scnt2[b][t];
            pres |= g_tpres2[b][t];
            tc   += g_tpart2[b][t];
        }
        int msk = (t < CC) && (cnt > 0) && pres;
        unsigned bal = __ballot_sync(0xffffffffu, msk);
        int nidx = __popc(bal);
        if (nidx < 1) nidx = 1;
        g_sScale[t] = msk ? 1.0f / (float)cnt : 0.f;
        float tdiv = (tc == 0.f) ? 100.f : tc;
        g_tScale[t] = msk ? 1.0f / tdiv : 0.f;
        if (t == 0) g_inv_nidx = 1.0f / (float)nidx;
    }

    if (t == 0) {
        g_loss = 0.0;
        double S1 = red[0], MSQ = sMSQ;
        double sum_l2 = 2.0 * (double)NT * S1 - 2.0 * MSQ;
        double bw = sum_l2 / ((double)NT * (double)NT - (double)NT);
        if (bw < 1e-6) bw = 1e-6;
        bw *= 0.25;
        g_chain = (bw >= 1e-6) ? 1 : 0;
        const double L2E = 1.4426950408889634;
        for (int i = 0; i < 5; i++) {
            double den = bw * (double)(1 << i);
            if (den < 1e-6) den = 1e-6;
            g_coef[i] = (float)(L2E / den);
        }
        g_c0 = g_coef[4];
    }
}

// ======================= K4: build signed weight vectors =======================
__global__ void k_buildV(const int* __restrict__ s_label, const float* __restrict__ t_label) {
    int i = blockIdx.x * 256 + threadIdx.x;
    float v[32];
    if (i < NB) {
#pragma unroll
        for (int c = 0; c < 32; c++) v[c] = 0.f;
        int lbl = s_label[i];
        if ((unsigned)lbl < CC) v[lbl] = g_sScale[lbl];
    } else {
        const float* tr = t_label + (size_t)(i - NB) * CC;
#pragma unroll
        for (int c = 0; c < CC; c++) v[c] = -tr[c] * g_tScale[c];
        v[31] = 0.f;
    }
    unsigned short* vh = g_Vh + (size_t)i * 32;
    unsigned short* vl = g_Vl + (size_t)i * 32;
#pragma unroll
    for (int c = 0; c < 32; c++) {
        __nv_bfloat16 hb = __float2bfloat16(v[c]);
        float rest = v[c] - __bfloat162float(hb);
        __nv_bfloat16 lb = __float2bfloat16(rest);
        unsigned short hu, lu; memcpy(&hu, &hb, 2); memcpy(&lu, &lb, 2);
        vh[c] = hu; vl[c] = lu;
    }
}

// ======================= K5: persistent main kernel =======================
__device__ __forceinline__ void decode_tile(int t, int* rA, int* rB, int* diag) {
    int ti = 0, rem = t;
    while (rem >= TILES - ti) { rem -= TILES - ti; ti++; }
    *rA = ti * 128; *rB = (ti + rem) * 128; *diag = (rem == 0);
}

__device__ __forceinline__ void issue_chunk(uint32_t sb, uint32_t stage,
                                            int rA, int rB, int chunk, int tid) {
    const unsigned short* gp[4] = {
        g_Xh + (size_t)rA * 256, g_Xl + (size_t)rA * 256,
        g_Xh + (size_t)rB * 256, g_Xl + (size_t)rB * 256 };
#pragma unroll
    for (int t = 0; t < 4; t++) {
#pragma unroll
        for (int q = 0; q < 2; q++) {
            int idx = q * 512 + tid;
            int row = idx >> 3, c16 = idx & 7;
            const unsigned short* src = gp[t] + row * 256 + chunk * 64 + c16 * 8;
            uint32_t dst = sb + stage + t * 16384 + row * 128 + ((c16 ^ (row & 7)) << 4);
            CP16(dst, src);
        }
    }
}

__device__ __forceinline__ void issue_v(uint32_t sb, int rA, int rB, int tid) {
    int row = tid >> 2, c16 = tid & 3;
    uint32_t rb = sb + row * 128;
    CP16(rb + SM_VA + ((c16 ^ (row & 7)) << 4),       g_Vh + (size_t)(rA + row) * 32 + c16 * 8);
    CP16(rb + SM_VA + (((c16 + 4) ^ (row & 7)) << 4), g_Vl + (size_t)(rA + row) * 32 + c16 * 8);
    CP16(rb + SM_VB + ((c16 ^ (row & 7)) << 4),       g_Vh + (size_t)(rB + row) * 32 + c16 * 8);
    CP16(rb + SM_VB + (((c16 + 4) ^ (row & 7)) << 4), g_Vl + (size_t)(rB + row) * 32 + c16 * 8);
}

__device__ __forceinline__ void do_mma(uint32_t aH, uint32_t aL, uint32_t bH, uint32_t bL,
                                       int wm, int wn, int lane, float acc[2][4][4]) {
    int r16 = lane & 15;
    int cuA = lane >> 4;
    int cuB = (lane >> 3) & 1;
    int jrow = (lane >> 4) * 8;
#pragma unroll
    for (int ks = 0; ks < 4; ks++) {
        uint32_t ah[2][4], al[2][4], bh[2][4], bl[2][4];
#pragma unroll
        for (int i = 0; i < 2; i++) {
            int row = wm * 32 + i * 16 + r16;
            uint32_t ro = (uint32_t)(row * 128 + (((ks * 2 + cuA) ^ (row & 7)) << 4));
            ldsm4(ah[i], aH + ro);
            ldsm4(al[i], aL + ro);
        }
#pragma unroll
        for (int p = 0; p < 2; p++) {
            int row = wn * 32 + p * 16 + jrow + (lane & 7);
            uint32_t ro = (uint32_t)(row * 128 + (((ks * 2 + cuB) ^ (row & 7)) << 4));
            ldsm4(bh[p], bH + ro);
            ldsm4(bl[p], bL + ro);
        }
#pragma unroll
        for (int i = 0; i < 2; i++)
#pragma unroll
            for (int j = 0; j < 4; j++) {
                const uint32_t* fh = &bh[j >> 1][(j & 1) * 2];
                const uint32_t* fl = &bl[j >> 1][(j & 1) * 2];
                mma16816(acc[i][j], ah[i], fh);
                mma16816(acc[i][j], ah[i], fl);
                mma16816(acc[i][j], al[i], fh);
            }
    }
}

__device__ __forceinline__ void do_mma_v(uint32_t vA, uint32_t vB,
                                         int wm, int wn, int lane, float acc[2][4][4]) {
    int r16 = lane & 15;
    int cuA = lane >> 4;
    int cuB = (lane >> 3) & 1;
    int jrow = (lane >> 4) * 8;
#pragma unroll
    for (int ks = 0; ks < 2; ks++) {
        uint32_t ah[2][4], al[2][4], bh[2][4], bl[2][4];
#pragma unroll
        for (int i = 0; i < 2; i++) {
            int row = wm * 32 + i * 16 + r16;
            uint32_t roh = (uint32_t)(row * 128 + (((ks * 2 + cuA) ^ (row & 7)) << 4));
            uint32_t rol = (uint32_t)(row * 128 + (((ks * 2 + cuA + 4) ^ (row & 7)) << 4));
            ldsm4(ah[i], vA + roh);
            ldsm4(al[i], vA + rol);
        }
#pragma unroll
        for (int p = 0; p < 2; p++) {
            int row = wn * 32 + p * 16 + jrow + (lane & 7);
            uint32_t roh = (uint32_t)(row * 128 + (((ks * 2 + cuB) ^ (row & 7)) << 4));
            uint32_t rol = (uint32_t)(row * 128 + (((ks * 2 + cuB + 4) ^ (row & 7)) << 4));
            ldsm4(bh[p], vB + roh);
            ldsm4(bl[p], vB + rol);
        }
#pragma unroll
        for (int i = 0; i < 2; i++)
#pragma unroll
            for (int j = 0; j < 4; j++) {
                const uint32_t* fh = &bh[j >> 1][(j & 1) * 2];
                const uint32_t* fl = &bl[j >> 1][(j & 1) * 2];
                mma16816(acc[i][j], ah[i], fh);
                mma16816(acc[i][j], ah[i], fl);
                mma16816(acc[i][j], al[i], fh);
            }
    }
}

__global__ void __launch_bounds__(512, 1) k_main() {
    extern __shared__ __align__(1024) char smem[];
    uint32_t sb = smem_u32(smem);
    int tid = threadIdx.x, wid = tid >> 5, lane = tid & 31;
    int wm = wid & 3, wn = wid >> 2;
    float* sred = (float*)(smem + SM_RED);

    int t = blockIdx.x;
    int rA, rB, diag;
    decode_tile(t, &rA, &rB, &diag);

    // prologue: V(t) + chunk0 -> stage0 ; chunk1 -> stage1
    issue_v(sb, rA, rB, tid);
    issue_chunk(sb, SM_S + 0 * STAGE, rA, rB, 0, tid);
    CP_COMMIT();
    issue_chunk(sb, SM_S + 1 * STAGE, rA, rB, 1, tid);
    CP_COMMIT();

    int sg = 0;   // stage of chunk about to be computed

    float c0 = g_c0;
    int chain = g_chain;
    float cf0 = 0, cf1 = 0, cf2 = 0, cf3 = 0, cf4 = 0;
    if (!chain) { cf0 = g_coef[0]; cf1 = g_coef[1]; cf2 = g_coef[2]; cf3 = g_coef[3]; cf4 = g_coef[4]; }

    for (;;) {
        int tn = t + NSM;
        int hasNext = (tn < NTILEPAIRS);
        int rAn = 0, rBn = 0, diagn = 0;
        if (hasNext) decode_tile(tn, &rAn, &rBn, &diagn);

        // prefetch sq values for this tile into registers (consumed at epilogue)
        float sqa_r[4], sqb_c[8];
#pragma unroll
        for (int i = 0; i < 2; i++)
#pragma unroll
            for (int rh = 0; rh < 2; rh++)
                sqa_r[i * 2 + rh] = g_sq[rA + wm * 32 + i * 16 + (lane >> 2) + rh * 8];
#pragma unroll
        for (int j = 0; j < 4; j++)
#pragma unroll
            for (int cc2 = 0; cc2 < 2; cc2++)
                sqb_c[j * 2 + cc2] = g_sq[rB + wn * 32 + j * 8 + (lane & 3) * 2 + cc2];

        float acc[2][4][4], wacc[2][4][4];
#pragma unroll
        for (int i = 0; i < 2; i++)
#pragma unroll
            for (int j = 0; j < 4; j++)
#pragma unroll
                for (int r = 0; r < 4; r++) { acc[i][j][r] = 0.f; wacc[i][j][r] = 0.f; }

#pragma unroll 1
        for (int c = 0; c < 4; c++) {
            if (c < 3 || hasNext) { CP_WAIT1(); } else { CP_WAIT0(); }
            __syncthreads();
            uint32_t nxtStage = sb + SM_S + ((sg + 2) % 3) * STAGE;
            if (c < 2) {
                issue_chunk(sb, nxtStage - sb, rA, rB, c + 2, tid);
                CP_COMMIT();
            } else if (hasNext) {
                if (c == 2) {
                    issue_v(sb, rAn, rBn, tid);                 // V buffer free: W-MMA done at c==0
                    issue_chunk(sb, nxtStage - sb, rAn, rBn, 0, tid);
                } else {
                    issue_chunk(sb, nxtStage - sb, rAn, rBn, 1, tid);
                }
                CP_COMMIT();
            }
            if (c == 0) do_mma_v(sb + SM_VA, sb + SM_VB, wm, wn, lane, wacc);
            uint32_t st = sb + SM_S + sg * STAGE;
            do_mma(st, st + 16384, st + 32768, st + 49152, wm, wn, lane, acc);
            sg = (sg + 1) % 3;
        }

        // ---- epilogue for tile t ----
        float part = 0.f;
#pragma unroll
        for (int i = 0; i < 2; i++)
#pragma unroll
            for (int j = 0; j < 4; j++)
#pragma unroll
                for (int r = 0; r < 4; r++) {
                    float l2 = fmaf(-2.0f, acc[i][j][r],
                                    sqa_r[i * 2 + (r >> 1)] + sqb_c[j * 2 + (r & 1)]);
                    l2 = fmaxf(l2, 0.0f);
                    float ks;
                    if (chain) {
                        float x  = ex2f(-l2 * c0);
                        float x2 = x * x, x4 = x2 * x2, x8 = x4 * x4;
                        ks = x + x2 + x4 + x8 + x8 * x8;
                    } else {
                        ks = ex2f(-l2 * cf0) + ex2f(-l2 * cf1) + ex2f(-l2 * cf2)
                           + ex2f(-l2 * cf3) + ex2f(-l2 * cf4);
                    }
                    part = fmaf(ks, wacc[i][j][r], part);
                }
        if (!diag) part *= 2.0f;

#pragma unroll
        for (int off = 16; off; off >>= 1) part += __shfl_xor_sync(0xffffffffu, part, off);
        if (lane == 0) sred[wid] = part;
        __syncthreads();
        if (tid == 0) {
            float s = 0.f;
#pragma unroll
            for (int w = 0; w < 16; w++) s += sred[w];
            atomicAdd(&g_loss, (double)s);
        }

        if (!hasNext) break;
        t = tn; rA = rAn; rB = rBn; diag = diagn;
    }
}

__global__ void k_out(float* out) {
    out[0] = (float)(g_loss * (double)g_inv_nidx);
}

// ======================= launch =======================
extern "C" void kernel_launch(void* const* d_in, const int* in_sizes, int n_in,
                              void* d_out, int out_size) {
    const float* src = (const float*)d_in[0];
    const float* tgt = (const float*)d_in[1];
    const int*   sl  = (const int*)d_in[2];
    const float* tl  = (const float*)d_in[3];
    float* out = (float*)d_out;

    cudaFuncSetAttribute(k_main, cudaFuncAttributeMaxDynamicSharedMemorySize, SMEM_TOTAL);

    k_prep<<<1024, 256>>>(src, tgt, sl, tl);
    k_reduce<<<96, 256>>>();
    k_finalize<<<1, 256>>>();
    k_buildV<<<32, 256>>>(sl, tl);
    k_main<<<NSM, 512, SMEM_TOTAL>>>();
    k_out<<<1, 1>>>(out);
}

// round 13
// speedup vs baseline: 4.6916x; 1.0385x over previous
#include <cuda_runtime.h>
#include <cuda_bf16.h>
#include <cstdint>
#include <cstring>
#include <math.h>

#define NB 4096
#define NT 8192
#define DD 256
#define CC 31
#define TILES 64
#define NTILEPAIRS 2080
#define NSM 148

// ======================= device scratch =======================
__device__ float  g_sq[NT];
__device__ float  g_colpart[1024][DD];
__device__ float  g_colpart2[64][DD];
__device__ float  g_tpart[512][32];
__device__ int    g_scnt_part[512][32];
__device__ int    g_tpres_part[512][32];
__device__ float  g_tpart2[32][32];
__device__ int    g_scnt2[32][32];
__device__ int    g_tpres2[32][32];
__device__ float  g_sScale[32];
__device__ float  g_tScale[32];
__device__ float  g_coef[5];
__device__ float  g_c0;
__device__ int    g_chain;
__device__ float  g_inv_nidx;
__device__ double g_loss;

__device__ __align__(16) unsigned short g_Xh[NT * DD];
__device__ __align__(16) unsigned short g_Xl[NT * DD];
__device__ __align__(16) unsigned short g_Vh[NT * 32];
__device__ __align__(16) unsigned short g_Vl[NT * 32];

// ======================= helpers =======================
__device__ __forceinline__ float ex2f(float x) {
    float y; asm("ex2.approx.ftz.f32 %0, %1;" : "=f"(y) : "f"(x)); return y;
}
__device__ __forceinline__ uint32_t smem_u32(const void* p) {
    uint32_t a;
    asm("{ .reg .u64 t; cvta.to.shared.u64 t, %1; cvt.u32.u64 %0, t; }" : "=r"(a) : "l"(p));
    return a;
}
#define CP16(dst, src) \
    asm volatile("cp.async.cg.shared.global [%0], [%1], 16;" :: "r"(dst), "l"(src))
#define MB_INIT(a, c) asm volatile("mbarrier.init.shared.b64 [%0], %1;" :: "r"(a), "r"(c) : "memory")
#define MB_ARRIVE(a)  asm volatile("mbarrier.arrive.shared.b64 _, [%0];" :: "r"(a) : "memory")
// .noinc is load-bearing: the default variant pre-increments the pending count
// (net-zero) and the barrier never completes -> R12 deadlock.
#define CP_MB_ARRIVE(a) asm volatile("cp.async.mbarrier.arrive.noinc.shared.b64 [%0];" :: "r"(a) : "memory")
#define FENCE_PROXY() asm volatile("fence.proxy.async.shared::cta;" ::: "memory")

#define MB_WAIT(addr, ph) do { \
    uint32_t _m = (addr), _p = (uint32_t)(ph), _d; \
    asm volatile("{\n\t.reg .pred p;\n\tmbarrier.try_wait.parity.acquire.cta.shared::cta.b64 p, [%1], %2;\n\tselp.b32 %0, 1, 0, p;\n\t}" \
        : "=r"(_d) : "r"(_m), "r"(_p) : "memory"); \
    if (!_d) { \
        asm volatile("{\n\t.reg .pred P1;\n\tWL%=:\n\tmbarrier.try_wait.parity.acquire.cta.shared::cta.b64 P1, [%0], %1, 0x989680;\n\t@P1 bra.uni WD%=;\n\tbra.uni WL%=;\n\tWD%=:\n\t}" \
            :: "r"(_m), "r"(_p) : "memory"); \
    } \
} while (0)

__device__ __forceinline__ void ldsm4(uint32_t r[4], uint32_t addr) {
    asm volatile("ldmatrix.sync.aligned.m8n8.x4.shared.b16 {%0,%1,%2,%3}, [%4];"
        : "=r"(r[0]), "=r"(r[1]), "=r"(r[2]), "=r"(r[3]) : "r"(addr));
}
__device__ __forceinline__ void mma16816(float d[4], const uint32_t a[4], const uint32_t b[2]) {
    asm volatile("mma.sync.aligned.m16n8k16.row.col.f32.bf16.bf16.f32 "
        "{%0,%1,%2,%3}, {%4,%5,%6,%7}, {%8,%9}, {%0,%1,%2,%3};"
        : "+f"(d[0]), "+f"(d[1]), "+f"(d[2]), "+f"(d[3])
        : "r"(a[0]), "r"(a[1]), "r"(a[2]), "r"(a[3]), "r"(b[0]), "r"(b[1]));
}

// ======================= smem layout (k_main) =======================
#define SM_VA   0
#define SM_VB   16384
#define SM_S    32768
#define STAGE   65536
#define SM_BAR  (32768 + 3 * STAGE)       // 229376
#define BAR_FULL(s)  (SM_BAR + (s) * 8)
#define BAR_EMPTY(s) (SM_BAR + 24 + (s) * 8)
#define BAR_VFULL    (SM_BAR + 48)
#define BAR_VEMPTY   (SM_BAR + 56)
#define SM_SRED      (SM_BAR + 64)
#define SMEM_TOTAL   (SM_SRED + 64)       // 229504

// ======================= K1: fused prepass (1024 CTAs) =======================
__global__ void __launch_bounds__(256) k_prep(
        const float* __restrict__ src, const float* __restrict__ tgt,
        const int* __restrict__ s_label, const float* __restrict__ t_label) {
    __shared__ float scol[8][DD];
    __shared__ float stsum[8][32];
    __shared__ int   sharg[8];
    __shared__ int   scnt[32];
    int b = blockIdx.x, t = threadIdx.x, w = t >> 5, l = t & 31;
    int row = b * 8 + w;
    const float* rp = (row < NB) ? src + (size_t)row * DD : tgt + (size_t)(row - NB) * DD;

    float4 x0 = *(const float4*)(rp + l * 8);
    float4 x1 = *(const float4*)(rp + l * 8 + 4);
    float xs[8] = {x0.x, x0.y, x0.z, x0.w, x1.x, x1.y, x1.z, x1.w};

    float s = 0.f;
#pragma unroll
    for (int k = 0; k < 8; k++) s = fmaf(xs[k], xs[k], s);
#pragma unroll
    for (int off = 16; off; off >>= 1) s += __shfl_xor_sync(0xffffffffu, s, off);
    if (l == 0) g_sq[row] = s;

    unsigned short h[8], lo[8];
#pragma unroll
    for (int k = 0; k < 8; k++) {
        __nv_bfloat16 hb = __float2bfloat16(xs[k]);
        float rest = xs[k] - __bfloat162float(hb);
        __nv_bfloat16 lb = __float2bfloat16(rest);
        memcpy(&h[k], &hb, 2); memcpy(&lo[k], &lb, 2);
    }
    size_t e = (size_t)row * DD + l * 8;
    *(uint2*)(g_Xh + e)     = make_uint2((uint32_t)h[0] | ((uint32_t)h[1] << 16),
                                         (uint32_t)h[2] | ((uint32_t)h[3] << 16));
    *(uint2*)(g_Xh + e + 4) = make_uint2((uint32_t)h[4] | ((uint32_t)h[5] << 16),
                                         (uint32_t)h[6] | ((uint32_t)h[7] << 16));
    *(uint2*)(g_Xl + e)     = make_uint2((uint32_t)lo[0] | ((uint32_t)lo[1] << 16),
                                         (uint32_t)lo[2] | ((uint32_t)lo[3] << 16));
    *(uint2*)(g_Xl + e + 4) = make_uint2((uint32_t)lo[4] | ((uint32_t)lo[5] << 16),
                                         (uint32_t)lo[6] | ((uint32_t)lo[7] << 16));

#pragma unroll
    for (int k = 0; k < 8; k++) scol[w][l * 8 + k] = xs[k];
    __syncthreads();
    {
        float m = 0.f;
#pragma unroll
        for (int ww = 0; ww < 8; ww++) m += scol[ww][t];
        g_colpart[b][t] = m;
    }

    if (b < 512) {
        if (t < 32) scnt[t] = 0;
        __syncthreads();
        if (l == 0) {
            int lbl = s_label[row];
            if ((unsigned)lbl < CC) atomicAdd(&scnt[lbl], 1);
        }
        __syncthreads();
        if (t < 32) g_scnt_part[b][t] = scnt[t];
    } else {
        int tb = b - 512;
        const float* tr = t_label + (size_t)(row - NB) * CC;
        float v = (l < CC) ? tr[l] : -1e30f;
        stsum[w][l] = (l < CC) ? v : 0.f;
        float bv = v; int bi = l;
#pragma unroll
        for (int off = 16; off; off >>= 1) {
            float ov = __shfl_xor_sync(0xffffffffu, bv, off);
            int   oi = __shfl_xor_sync(0xffffffffu, bi, off);
            if (ov > bv || (ov == bv && oi < bi)) { bv = ov; bi = oi; }
        }
        if (l == 0) sharg[w] = bi;
        __syncthreads();
        if (t < 32) {
            float tc = 0.f; int pres = 0;
#pragma unroll
            for (int ww = 0; ww < 8; ww++) {
                tc += stsum[ww][t];
                pres |= (sharg[ww] == t);
            }
            g_tpart[tb][t] = tc;
            g_tpres_part[tb][t] = pres;
        }
    }
}

// ======================= K2: parallel partial fold (96 CTAs) =======================
__global__ void __launch_bounds__(256) k_reduce() {
    int b = blockIdx.x, t = threadIdx.x;
    if (b < 64) {
        float m = 0.f;
#pragma unroll
        for (int r = 0; r < 16; r++) m += g_colpart[b * 16 + r][t];
        g_colpart2[b][t] = m;
    } else {
        int rb = b - 64;
        if (t < 32) {
            int cnt = 0, pres = 0;
            float tc = 0.f;
#pragma unroll
            for (int r = 0; r < 16; r++) {
                int blk = rb * 16 + r;
                cnt  += g_scnt_part[blk][t];
                pres |= g_tpres_part[blk][t];
                tc   += g_tpart[blk][t];
            }
            g_scnt2[rb][t] = cnt;
            g_tpres2[rb][t] = pres;
            g_tpart2[rb][t] = tc;
        }
    }
}

// ======================= K3: finalize scalars =======================
__global__ void k_finalize() {
    __shared__ double red[256];
    __shared__ double sMSQ;
    int t = threadIdx.x;

    float m = 0.f;
#pragma unroll
    for (int b = 0; b < 64; b++) m += g_colpart2[b][t];
    red[t] = (double)m * (double)m;
    __syncthreads();
    for (int off = 128; off; off >>= 1) { if (t < off) red[t] += red[t + off]; __syncthreads(); }
    if (t == 0) sMSQ = red[0];
    __syncthreads();

    double s1 = 0.0;
    for (int r = t; r < NT; r += 256) s1 += (double)g_sq[r];
    red[t] = s1;
    __syncthreads();
    for (int off = 128; off; off >>= 1) { if (t < off) red[t] += red[t + off]; __syncthreads(); }

    if (t < 32) {
        int cnt = 0, pres = 0;
        float tc = 0.f;
#pragma unroll
        for (int b = 0; b < 32; b++) {
            cnt  += g_scnt2[b][t];
            pres |= g_tpres2[b][t];
            tc   += g_tpart2[b][t];
        }
        int msk = (t < CC) && (cnt > 0) && pres;
        unsigned bal = __ballot_sync(0xffffffffu, msk);
        int nidx = __popc(bal);
        if (nidx < 1) nidx = 1;
        g_sScale[t] = msk ? 1.0f / (float)cnt : 0.f;
        float tdiv = (tc == 0.f) ? 100.f : tc;
        g_tScale[t] = msk ? 1.0f / tdiv : 0.f;
        if (t == 0) g_inv_nidx = 1.0f / (float)nidx;
    }

    if (t == 0) {
        g_loss = 0.0;
        double S1 = red[0], MSQ = sMSQ;
        double sum_l2 = 2.0 * (double)NT * S1 - 2.0 * MSQ;
        double bw = sum_l2 / ((double)NT * (double)NT - (double)NT);
        if (bw < 1e-6) bw = 1e-6;
        bw *= 0.25;
        g_chain = (bw >= 1e-6) ? 1 : 0;
        const double L2E = 1.4426950408889634;
        for (int i = 0; i < 5; i++) {
            double den = bw * (double)(1 << i);
            if (den < 1e-6) den = 1e-6;
            g_coef[i] = (float)(L2E / den);
        }
        g_c0 = g_coef[4];
    }
}

// ======================= K4: build signed weight vectors =======================
__global__ void k_buildV(const int* __restrict__ s_label, const float* __restrict__ t_label) {
    int i = blockIdx.x * 256 + threadIdx.x;
    float v[32];
    if (i < NB) {
#pragma unroll
        for (int c = 0; c < 32; c++) v[c] = 0.f;
        int lbl = s_label[i];
        if ((unsigned)lbl < CC) v[lbl] = g_sScale[lbl];
    } else {
        const float* tr = t_label + (size_t)(i - NB) * CC;
#pragma unroll
        for (int c = 0; c < CC; c++) v[c] = -tr[c] * g_tScale[c];
        v[31] = 0.f;
    }
    unsigned short* vh = g_Vh + (size_t)i * 32;
    unsigned short* vl = g_Vl + (size_t)i * 32;
#pragma unroll
    for (int c = 0; c < 32; c++) {
        __nv_bfloat16 hb = __float2bfloat16(v[c]);
        float rest = v[c] - __bfloat162float(hb);
        __nv_bfloat16 lb = __float2bfloat16(rest);
        unsigned short hu, lu; memcpy(&hu, &hb, 2); memcpy(&lu, &lb, 2);
        vh[c] = hu; vl[c] = lu;
    }
}

// ======================= K5: persistent main, mbarrier pipeline =======================
__device__ __forceinline__ void decode_rows(int t, int* rA, int* rB, int* diag) {
    int ti = 0, rem = t;
    while (rem >= TILES - ti) { rem -= TILES - ti; ti++; }
    *rA = ti * 128; *rB = (ti + rem) * 128; *diag = (rem == 0);
}

__device__ __forceinline__ void issue_chunk(uint32_t sb, uint32_t stage,
                                            int rA, int rB, int chunk, int tid) {
    const unsigned short* gp[4] = {
        g_Xh + (size_t)rA * 256, g_Xl + (size_t)rA * 256,
        g_Xh + (size_t)rB * 256, g_Xl + (size_t)rB * 256 };
#pragma unroll
    for (int t = 0; t < 4; t++) {
#pragma unroll
        for (int q = 0; q < 2; q++) {
            int idx = q * 512 + tid;
            int row = idx >> 3, c16 = idx & 7;
            const unsigned short* src = gp[t] + row * 256 + chunk * 64 + c16 * 8;
            uint32_t dst = sb + stage + t * 16384 + row * 128 + ((c16 ^ (row & 7)) << 4);
            CP16(dst, src);
        }
    }
}

__device__ __forceinline__ void issue_v(uint32_t sb, int rA, int rB, int tid) {
    int row = tid >> 2, c16 = tid & 3;
    uint32_t rb = sb + row * 128;
    CP16(rb + SM_VA + ((c16 ^ (row & 7)) << 4),       g_Vh + (size_t)(rA + row) * 32 + c16 * 8);
    CP16(rb + SM_VA + (((c16 + 4) ^ (row & 7)) << 4), g_Vl + (size_t)(rA + row) * 32 + c16 * 8);
    CP16(rb + SM_VB + ((c16 ^ (row & 7)) << 4),       g_Vh + (size_t)(rB + row) * 32 + c16 * 8);
    CP16(rb + SM_VB + (((c16 + 4) ^ (row & 7)) << 4), g_Vl + (size_t)(rB + row) * 32 + c16 * 8);
}

__device__ __forceinline__ void do_mma(uint32_t aH, uint32_t aL, uint32_t bH, uint32_t bL,
                                       int wm, int wn, int lane, float acc[2][4][4]) {
    int r16 = lane & 15;
    int cuA = lane >> 4;
    int cuB = (lane >> 3) & 1;
    int jrow = (lane >> 4) * 8;
#pragma unroll
    for (int ks = 0; ks < 4; ks++) {
        uint32_t ah[2][4], al[2][4], bh[2][4], bl[2][4];
#pragma unroll
        for (int i = 0; i < 2; i++) {
            int row = wm * 32 + i * 16 + r16;
            uint32_t ro = (uint32_t)(row * 128 + (((ks * 2 + cuA) ^ (row & 7)) << 4));
            ldsm4(ah[i], aH + ro);
            ldsm4(al[i], aL + ro);
        }
#pragma unroll
        for (int p = 0; p < 2; p++) {
            int row = wn * 32 + p * 16 + jrow + (lane & 7);
            uint32_t ro = (uint32_t)(row * 128 + (((ks * 2 + cuB) ^ (row & 7)) << 4));
            ldsm4(bh[p], bH + ro);
            ldsm4(bl[p], bL + ro);
        }
#pragma unroll
        for (int i = 0; i < 2; i++)
#pragma unroll
            for (int j = 0; j < 4; j++) {
                const uint32_t* fh = &bh[j >> 1][(j & 1) * 2];
                const uint32_t* fl = &bl[j >> 1][(j & 1) * 2];
                mma16816(acc[i][j], ah[i], fh);
                mma16816(acc[i][j], ah[i], fl);
                mma16816(acc[i][j], al[i], fh);
            }
    }
}

__device__ __forceinline__ void do_mma_v(uint32_t vA, uint32_t vB,
                                         int wm, int wn, int lane, float acc[2][4][4]) {
    int r16 = lane & 15;
    int cuA = lane >> 4;
    int cuB = (lane >> 3) & 1;
    int jrow = (lane >> 4) * 8;
#pragma unroll
    for (int ks = 0; ks < 2; ks++) {
        uint32_t ah[2][4], al[2][4], bh[2][4], bl[2][4];
#pragma unroll
        for (int i = 0; i < 2; i++) {
            int row = wm * 32 + i * 16 + r16;
            uint32_t roh = (uint32_t)(row * 128 + (((ks * 2 + cuA) ^ (row & 7)) << 4));
            uint32_t rol = (uint32_t)(row * 128 + (((ks * 2 + cuA + 4) ^ (row & 7)) << 4));
            ldsm4(ah[i], vA + roh);
            ldsm4(al[i], vA + rol);
        }
#pragma unroll
        for (int p = 0; p < 2; p++) {
            int row = wn * 32 + p * 16 + jrow + (lane & 7);
            uint32_t roh = (uint32_t)(row * 128 + (((ks * 2 + cuB) ^ (row & 7)) << 4));
            uint32_t rol = (uint32_t)(row * 128 + (((ks * 2 + cuB + 4) ^ (row & 7)) << 4));
            ldsm4(bh[p], vB + roh);
            ldsm4(bl[p], vB + rol);
        }
#pragma unroll
        for (int i = 0; i < 2; i++)
#pragma unroll
            for (int j = 0; j < 4; j++) {
                const uint32_t* fh = &bh[j >> 1][(j & 1) * 2];
                const uint32_t* fl = &bl[j >> 1][(j & 1) * 2];
                mma16816(acc[i][j], ah[i], fh);
                mma16816(acc[i][j], ah[i], fl);
                mma16816(acc[i][j], al[i], fh);
            }
    }
}

__global__ void __launch_bounds__(512, 1) k_main() {
    extern __shared__ __align__(1024) char smem[];
    uint32_t sb = smem_u32(smem);
    int tid = threadIdx.x, wid = tid >> 5, lane = tid & 31;
    int wm = wid & 3, wn = wid >> 2;
    float* sred = (float*)(smem + SM_SRED);

    if (tid == 0) {
        MB_INIT(sb + BAR_FULL(0), 512); MB_INIT(sb + BAR_FULL(1), 512); MB_INIT(sb + BAR_FULL(2), 512);
        MB_INIT(sb + BAR_EMPTY(0), 16); MB_INIT(sb + BAR_EMPTY(1), 16); MB_INIT(sb + BAR_EMPTY(2), 16);
        MB_INIT(sb + BAR_VFULL, 512);   MB_INIT(sb + BAR_VEMPTY, 16);
    }
    __syncthreads();

    int ntiles = (NTILEPAIRS - 1 - (int)blockIdx.x) / NSM + 1;
    int nch = ntiles * 4;

    float c0 = g_c0;
    int chain = g_chain;
    float cf0 = 0, cf1 = 0, cf2 = 0, cf3 = 0, cf4 = 0;
    if (!chain) { cf0 = g_coef[0]; cf1 = g_coef[1]; cf2 = g_coef[2]; cf3 = g_coef[3]; cf4 = g_coef[4]; }

    int prA, prB, pd;
    int crA = 0, crB = 0, cdiag = 0;
    decode_rows(blockIdx.x, &prA, &prB, &pd);

    // prologue: V(t0), chunk0 -> s0, chunk1 -> s1
    MB_WAIT(sb + BAR_VEMPTY, 1);
    FENCE_PROXY();
    issue_v(sb, prA, prB, tid);
    CP_MB_ARRIVE(sb + BAR_VFULL);
    MB_WAIT(sb + BAR_EMPTY(0), 1);
    issue_chunk(sb, SM_S + 0 * STAGE, prA, prB, 0, tid);
    CP_MB_ARRIVE(sb + BAR_FULL(0));
    MB_WAIT(sb + BAR_EMPTY(1), 1);
    issue_chunk(sb, SM_S + 1 * STAGE, prA, prB, 1, tid);
    CP_MB_ARRIVE(sb + BAR_FULL(1));

    float total = 0.f;
    float acc[2][4][4], wacc[2][4][4];
    float sqa_r[4], sqb_c[8];

#pragma unroll 1
    for (int g = 0; g < nch; g++) {
        // ---- produce chunk g+2 ----
        int gp = g + 2;
        if (gp < nch) {
            int ps = gp % 3, pj = gp & 3;
            if (pj == 0) {
                int lt = gp >> 2;
                decode_rows((int)blockIdx.x + lt * NSM, &prA, &prB, &pd);
                MB_WAIT(sb + BAR_VEMPTY, (lt + 1) & 1);
                FENCE_PROXY();
                issue_v(sb, prA, prB, tid);
            }
            MB_WAIT(sb + BAR_EMPTY(ps), ((gp / 3) + 1) & 1);
            FENCE_PROXY();
            issue_chunk(sb, SM_S + ps * STAGE, prA, prB, pj, tid);
            CP_MB_ARRIVE(sb + BAR_FULL(ps));
            if (pj == 0) CP_MB_ARRIVE(sb + BAR_VFULL);
        }

        // ---- consume chunk g ----
        int cs = g % 3, j = g & 3;
        if (j == 0) {
            int lt = g >> 2;
            decode_rows((int)blockIdx.x + lt * NSM, &crA, &crB, &cdiag);
#pragma unroll
            for (int i = 0; i < 2; i++)
#pragma unroll
                for (int jj = 0; jj < 4; jj++)
#pragma unroll
                    for (int r = 0; r < 4; r++) { acc[i][jj][r] = 0.f; wacc[i][jj][r] = 0.f; }
#pragma unroll
            for (int i = 0; i < 2; i++)
#pragma unroll
                for (int rh = 0; rh < 2; rh++)
                    sqa_r[i * 2 + rh] = g_sq[crA + wm * 32 + i * 16 + (lane >> 2) + rh * 8];
#pragma unroll
            for (int jj = 0; jj < 4; jj++)
#pragma unroll
                for (int cc2 = 0; cc2 < 2; cc2++)
                    sqb_c[jj * 2 + cc2] = g_sq[crB + wn * 32 + jj * 8 + (lane & 3) * 2 + cc2];

            MB_WAIT(sb + BAR_VFULL, lt & 1);
            do_mma_v(sb + SM_VA, sb + SM_VB, wm, wn, lane, wacc);
            if (lane == 0) MB_ARRIVE(sb + BAR_VEMPTY);
        }

        MB_WAIT(sb + BAR_FULL(cs), (g / 3) & 1);
        uint32_t st = sb + SM_S + cs * STAGE;
        do_mma(st, st + 16384, st + 32768, st + 49152, wm, wn, lane, acc);
        if (lane == 0) MB_ARRIVE(sb + BAR_EMPTY(cs));

        if (j == 3) {
            float part = 0.f;
#pragma unroll
            for (int i = 0; i < 2; i++)
#pragma unroll
                for (int jj = 0; jj < 4; jj++)
#pragma unroll
                    for (int r = 0; r < 4; r++) {
                        float l2 = fmaf(-2.0f, acc[i][jj][r],
                                        sqa_r[i * 2 + (r >> 1)] + sqb_c[jj * 2 + (r & 1)]);
                        l2 = fmaxf(l2, 0.0f);
                        float ks;
                        if (chain) {
                            float x  = ex2f(-l2 * c0);
                            float x2 = x * x, x4 = x2 * x2, x8 = x4 * x4;
                            ks = x + x2 + x4 + x8 + x8 * x8;
                        } else {
                            ks = ex2f(-l2 * cf0) + ex2f(-l2 * cf1) + ex2f(-l2 * cf2)
                               + ex2f(-l2 * cf3) + ex2f(-l2 * cf4);
                        }
                        part = fmaf(ks, wacc[i][jj][r], part);
                    }
            if (!cdiag) part *= 2.0f;
            total += part;
        }
    }

    // ---- one reduction + atomic per CTA ----
#pragma unroll
    for (int off = 16; off; off >>= 1) total += __shfl_xor_sync(0xffffffffu, total, off);
    if (lane == 0) sred[wid] = total;
    __syncthreads();
    if (tid == 0) {
        float s = 0.f;
#pragma unroll
        for (int w = 0; w < 16; w++) s += sred[w];
        atomicAdd(&g_loss, (double)s);
    }
}

__global__ void k_out(float* out) {
    out[0] = (float)(g_loss * (double)g_inv_nidx);
}

// ======================= launch =======================
extern "C" void kernel_launch(void* const* d_in, const int* in_sizes, int n_in,
                              void* d_out, int out_size) {
    const float* src = (const float*)d_in[0];
    const float* tgt = (const float*)d_in[1];
    const int*   sl  = (const int*)d_in[2];
    const float* tl  = (const float*)d_in[3];
    float* out = (float*)d_out;

    cudaFuncSetAttribute(k_main, cudaFuncAttributeMaxDynamicSharedMemorySize, SMEM_TOTAL);

    k_prep<<<1024, 256>>>(src, tgt, sl, tl);
    k_reduce<<<96, 256>>>();
    k_finalize<<<1, 256>>>();
    k_buildV<<<32, 256>>>(sl, tl);
    k_main<<<NSM, 512, SMEM_TOTAL>>>();
    k_out<<<1, 1>>>(out);
}

// round 14
// speedup vs baseline: 4.8766x; 1.0394x over previous
#include <cuda_runtime.h>
#include <cuda_bf16.h>
#include <cstdint>
#include <cstring>
#include <math.h>

#define NB 4096
#define NT 8192
#define DD 256
#define CC 31
#define TILES 64
#define NTILEPAIRS 2080
#define NSM 148

// ======================= device scratch =======================
__device__ float  g_sq[NT];
__device__ float  g_colpart[1024][DD];
__device__ float  g_colpart2[64][DD];
__device__ float  g_tpart[512][32];
__device__ int    g_scnt_part[512][32];
__device__ int    g_tpres_part[512][32];
__device__ float  g_tpart2[32][32];
__device__ int    g_scnt2[32][32];
__device__ int    g_tpres2[32][32];
__device__ float  g_sScale[32];
__device__ float  g_tScale[32];
__device__ float  g_coef[5];
__device__ float  g_c0;
__device__ int    g_chain;
__device__ float  g_inv_nidx;
__device__ double g_loss;

__device__ __align__(16) unsigned short g_Xh[NT * DD];
__device__ __align__(16) unsigned short g_Xl[NT * DD];
__device__ __align__(16) unsigned short g_Vh[NT * 32];
__device__ __align__(16) unsigned short g_Vl[NT * 32];

// ======================= helpers =======================
__device__ __forceinline__ float ex2f(float x) {
    float y; asm("ex2.approx.ftz.f32 %0, %1;" : "=f"(y) : "f"(x)); return y;
}
__device__ __forceinline__ uint32_t smem_u32(const void* p) {
    uint32_t a;
    asm("{ .reg .u64 t; cvta.to.shared.u64 t, %1; cvt.u32.u64 %0, t; }" : "=r"(a) : "l"(p));
    return a;
}
#define CP16(dst, src) \
    asm volatile("cp.async.cg.shared.global [%0], [%1], 16;" :: "r"(dst), "l"(src))
#define MB_INIT(a, c) asm volatile("mbarrier.init.shared.b64 [%0], %1;" :: "r"(a), "r"(c) : "memory")
#define MB_ARRIVE(a)  asm volatile("mbarrier.arrive.shared.b64 _, [%0];" :: "r"(a) : "memory")
// .noinc is load-bearing: the default variant pre-increments the pending count
// (net-zero) and the barrier never completes -> R12 deadlock.
#define CP_MB_ARRIVE(a) asm volatile("cp.async.mbarrier.arrive.noinc.shared.b64 [%0];" :: "r"(a) : "memory")
#define FENCE_PROXY() asm volatile("fence.proxy.async.shared::cta;" ::: "memory")

#define MB_WAIT(addr, ph) do { \
    uint32_t _m = (addr), _p = (uint32_t)(ph), _d; \
    asm volatile("{\n\t.reg .pred p;\n\tmbarrier.try_wait.parity.acquire.cta.shared::cta.b64 p, [%1], %2;\n\tselp.b32 %0, 1, 0, p;\n\t}" \
        : "=r"(_d) : "r"(_m), "r"(_p) : "memory"); \
    if (!_d) { \
        asm volatile("{\n\t.reg .pred P1;\n\tWL%=:\n\tmbarrier.try_wait.parity.acquire.cta.shared::cta.b64 P1, [%0], %1, 0x989680;\n\t@P1 bra.uni WD%=;\n\tbra.uni WL%=;\n\tWD%=:\n\t}" \
            :: "r"(_m), "r"(_p) : "memory"); \
    } \
} while (0)

__device__ __forceinline__ void ldsm4(uint32_t r[4], uint32_t addr) {
    asm volatile("ldmatrix.sync.aligned.m8n8.x4.shared.b16 {%0,%1,%2,%3}, [%4];"
        : "=r"(r[0]), "=r"(r[1]), "=r"(r[2]), "=r"(r[3]) : "r"(addr));
}
__device__ __forceinline__ void mma16816(float d[4], const uint32_t a[4], const uint32_t b[2]) {
    asm volatile("mma.sync.aligned.m16n8k16.row.col.f32.bf16.bf16.f32 "
        "{%0,%1,%2,%3}, {%4,%5,%6,%7}, {%8,%9}, {%0,%1,%2,%3};"
        : "+f"(d[0]), "+f"(d[1]), "+f"(d[2]), "+f"(d[3])
        : "r"(a[0]), "r"(a[1]), "r"(a[2]), "r"(a[3]), "r"(b[0]), "r"(b[1]));
}

// ======================= smem layout (k_main) =======================
#define SM_VA   0
#define SM_VB   16384
#define SM_S    32768
#define STAGE   65536
#define SM_BAR  (32768 + 3 * STAGE)       // 229376
#define BAR_FULL(s)  (SM_BAR + (s) * 8)
#define BAR_EMPTY(s) (SM_BAR + 24 + (s) * 8)
#define BAR_VFULL    (SM_BAR + 48)
#define BAR_VEMPTY   (SM_BAR + 56)
#define SM_SRED      (SM_BAR + 64)
#define SMEM_TOTAL   (SM_SRED + 64)       // 229504

// ======================= K1: fused prepass (1024 CTAs) =======================
__global__ void __launch_bounds__(256) k_prep(
        const float* __restrict__ src, const float* __restrict__ tgt,
        const int* __restrict__ s_label, const float* __restrict__ t_label) {
    __shared__ float scol[8][DD];
    __shared__ float stsum[8][32];
    __shared__ int   sharg[8];
    __shared__ int   scnt[32];
    int b = blockIdx.x, t = threadIdx.x, w = t >> 5, l = t & 31;
    int row = b * 8 + w;
    const float* rp = (row < NB) ? src + (size_t)row * DD : tgt + (size_t)(row - NB) * DD;

    float4 x0 = *(const float4*)(rp + l * 8);
    float4 x1 = *(const float4*)(rp + l * 8 + 4);
    float xs[8] = {x0.x, x0.y, x0.z, x0.w, x1.x, x1.y, x1.z, x1.w};

    float s = 0.f;
#pragma unroll
    for (int k = 0; k < 8; k++) s = fmaf(xs[k], xs[k], s);
#pragma unroll
    for (int off = 16; off; off >>= 1) s += __shfl_xor_sync(0xffffffffu, s, off);
    if (l == 0) g_sq[row] = s;

    unsigned short h[8], lo[8];
#pragma unroll
    for (int k = 0; k < 8; k++) {
        __nv_bfloat16 hb = __float2bfloat16(xs[k]);
        float rest = xs[k] - __bfloat162float(hb);
        __nv_bfloat16 lb = __float2bfloat16(rest);
        memcpy(&h[k], &hb, 2); memcpy(&lo[k], &lb, 2);
    }
    size_t e = (size_t)row * DD + l * 8;
    *(uint2*)(g_Xh + e)     = make_uint2((uint32_t)h[0] | ((uint32_t)h[1] << 16),
                                         (uint32_t)h[2] | ((uint32_t)h[3] << 16));
    *(uint2*)(g_Xh + e + 4) = make_uint2((uint32_t)h[4] | ((uint32_t)h[5] << 16),
                                         (uint32_t)h[6] | ((uint32_t)h[7] << 16));
    *(uint2*)(g_Xl + e)     = make_uint2((uint32_t)lo[0] | ((uint32_t)lo[1] << 16),
                                         (uint32_t)lo[2] | ((uint32_t)lo[3] << 16));
    *(uint2*)(g_Xl + e + 4) = make_uint2((uint32_t)lo[4] | ((uint32_t)lo[5] << 16),
                                         (uint32_t)lo[6] | ((uint32_t)lo[7] << 16));

#pragma unroll
    for (int k = 0; k < 8; k++) scol[w][l * 8 + k] = xs[k];
    __syncthreads();
    {
        float m = 0.f;
#pragma unroll
        for (int ww = 0; ww < 8; ww++) m += scol[ww][t];
        g_colpart[b][t] = m;
    }

    if (b < 512) {
        if (t < 32) scnt[t] = 0;
        __syncthreads();
        if (l == 0) {
            int lbl = s_label[row];
            if ((unsigned)lbl < CC) atomicAdd(&scnt[lbl], 1);
        }
        __syncthreads();
        if (t < 32) g_scnt_part[b][t] = scnt[t];
    } else {
        int tb = b - 512;
        const float* tr = t_label + (size_t)(row - NB) * CC;
        float v = (l < CC) ? tr[l] : -1e30f;
        stsum[w][l] = (l < CC) ? v : 0.f;
        float bv = v; int bi = l;
#pragma unroll
        for (int off = 16; off; off >>= 1) {
            float ov = __shfl_xor_sync(0xffffffffu, bv, off);
            int   oi = __shfl_xor_sync(0xffffffffu, bi, off);
            if (ov > bv || (ov == bv && oi < bi)) { bv = ov; bi = oi; }
        }
        if (l == 0) sharg[w] = bi;
        __syncthreads();
        if (t < 32) {
            float tc = 0.f; int pres = 0;
#pragma unroll
            for (int ww = 0; ww < 8; ww++) {
                tc += stsum[ww][t];
                pres |= (sharg[ww] == t);
            }
            g_tpart[tb][t] = tc;
            g_tpres_part[tb][t] = pres;
        }
    }
}

// ======================= K2: parallel partial fold (96 CTAs) =======================
__global__ void __launch_bounds__(256) k_reduce() {
    int b = blockIdx.x, t = threadIdx.x;
    if (b < 64) {
        float m = 0.f;
#pragma unroll
        for (int r = 0; r < 16; r++) m += g_colpart[b * 16 + r][t];
        g_colpart2[b][t] = m;
    } else {
        int rb = b - 64;
        if (t < 32) {
            int cnt = 0, pres = 0;
            float tc = 0.f;
#pragma unroll
            for (int r = 0; r < 16; r++) {
                int blk = rb * 16 + r;
                cnt  += g_scnt_part[blk][t];
                pres |= g_tpres_part[blk][t];
                tc   += g_tpart[blk][t];
            }
            g_scnt2[rb][t] = cnt;
            g_tpres2[rb][t] = pres;
            g_tpart2[rb][t] = tc;
        }
    }
}

// ======================= K3: finalize scalars =======================
__global__ void k_finalize() {
    __shared__ double red[256];
    __shared__ double sMSQ;
    int t = threadIdx.x;

    float m = 0.f;
#pragma unroll
    for (int b = 0; b < 64; b++) m += g_colpart2[b][t];
    red[t] = (double)m * (double)m;
    __syncthreads();
    for (int off = 128; off; off >>= 1) { if (t < off) red[t] += red[t + off]; __syncthreads(); }
    if (t == 0) sMSQ = red[0];
    __syncthreads();

    double s1 = 0.0;
    for (int r = t; r < NT; r += 256) s1 += (double)g_sq[r];
    red[t] = s1;
    __syncthreads();
    for (int off = 128; off; off >>= 1) { if (t < off) red[t] += red[t + off]; __syncthreads(); }

    if (t < 32) {
        int cnt = 0, pres = 0;
        float tc = 0.f;
#pragma unroll
        for (int b = 0; b < 32; b++) {
            cnt  += g_scnt2[b][t];
            pres |= g_tpres2[b][t];
            tc   += g_tpart2[b][t];
        }
        int msk = (t < CC) && (cnt > 0) && pres;
        unsigned bal = __ballot_sync(0xffffffffu, msk);
        int nidx = __popc(bal);
        if (nidx < 1) nidx = 1;
        g_sScale[t] = msk ? 1.0f / (float)cnt : 0.f;
        float tdiv = (tc == 0.f) ? 100.f : tc;
        g_tScale[t] = msk ? 1.0f / tdiv : 0.f;
        if (t == 0) g_inv_nidx = 1.0f / (float)nidx;
    }

    if (t == 0) {
        g_loss = 0.0;
        double S1 = red[0], MSQ = sMSQ;
        double sum_l2 = 2.0 * (double)NT * S1 - 2.0 * MSQ;
        double bw = sum_l2 / ((double)NT * (double)NT - (double)NT);
        if (bw < 1e-6) bw = 1e-6;
        bw *= 0.25;
        g_chain = (bw >= 1e-6) ? 1 : 0;
        const double L2E = 1.4426950408889634;
        for (int i = 0; i < 5; i++) {
            double den = bw * (double)(1 << i);
            if (den < 1e-6) den = 1e-6;
            g_coef[i] = (float)(L2E / den);
        }
        g_c0 = g_coef[4];
    }
}

// ======================= K4: build signed weight vectors (warp per row) =========
__global__ void __launch_bounds__(256) k_buildV(const int* __restrict__ s_label,
                                                const float* __restrict__ t_label) {
    int w = threadIdx.x >> 5, l = threadIdx.x & 31;
    int row = blockIdx.x * 8 + w;        // grid 1024 -> rows 0..8191
    float v;
    if (row < NB) {
        int lbl = s_label[row];          // uniform within warp's row
        v = (l == lbl && (unsigned)lbl < CC) ? g_sScale[lbl] : 0.f;
    } else {
        const float* tr = t_label + (size_t)(row - NB) * CC;
        v = (l < CC) ? -tr[l] * g_tScale[l] : 0.f;
    }
    __nv_bfloat16 hb = __float2bfloat16(v);
    float rest = v - __bfloat162float(hb);
    __nv_bfloat16 lb = __float2bfloat16(rest);
    unsigned short hu, lu; memcpy(&hu, &hb, 2); memcpy(&lu, &lb, 2);
    g_Vh[(size_t)row * 32 + l] = hu;
    g_Vl[(size_t)row * 32 + l] = lu;
}

// ======================= K5: persistent main, mbarrier pipeline =======================
__device__ __forceinline__ void decode_rows(int t, int* rA, int* rB, int* diag) {
    int ti = 0, rem = t;
    while (rem >= TILES - ti) { rem -= TILES - ti; ti++; }
    *rA = ti * 128; *rB = (ti + rem) * 128; *diag = (rem == 0);
}

__device__ __forceinline__ void issue_chunk(uint32_t sb, uint32_t stage,
                                            int rA, int rB, int chunk, int tid) {
    const unsigned short* gp[4] = {
        g_Xh + (size_t)rA * 256, g_Xl + (size_t)rA * 256,
        g_Xh + (size_t)rB * 256, g_Xl + (size_t)rB * 256 };
#pragma unroll
    for (int t = 0; t < 4; t++) {
#pragma unroll
        for (int q = 0; q < 2; q++) {
            int idx = q * 512 + tid;
            int row = idx >> 3, c16 = idx & 7;
            const unsigned short* src = gp[t] + row * 256 + chunk * 64 + c16 * 8;
            uint32_t dst = sb + stage + t * 16384 + row * 128 + ((c16 ^ (row & 7)) << 4);
            CP16(dst, src);
        }
    }
}

__device__ __forceinline__ void issue_v(uint32_t sb, int rA, int rB, int tid) {
    int row = tid >> 2, c16 = tid & 3;
    uint32_t rb = sb + row * 128;
    CP16(rb + SM_VA + ((c16 ^ (row & 7)) << 4),       g_Vh + (size_t)(rA + row) * 32 + c16 * 8);
    CP16(rb + SM_VA + (((c16 + 4) ^ (row & 7)) << 4), g_Vl + (size_t)(rA + row) * 32 + c16 * 8);
    CP16(rb + SM_VB + ((c16 ^ (row & 7)) << 4),       g_Vh + (size_t)(rB + row) * 32 + c16 * 8);
    CP16(rb + SM_VB + (((c16 + 4) ^ (row & 7)) << 4), g_Vl + (size_t)(rB + row) * 32 + c16 * 8);
}

// Gram 3-product, B fragments loaded in j-halves to expose independent LDSM->MMA overlap.
__device__ __forceinline__ void do_mma(uint32_t aH, uint32_t aL, uint32_t bH, uint32_t bL,
                                       int wm, int wn, int lane, float acc[2][4][4]) {
    int r16 = lane & 15;
    int cuA = lane >> 4;
    int cuB = (lane >> 3) & 1;
    int jrow = (lane >> 4) * 8;
#pragma unroll
    for (int ks = 0; ks < 4; ks++) {
        uint32_t ah[2][4], al[2][4];
#pragma unroll
        for (int i = 0; i < 2; i++) {
            int row = wm * 32 + i * 16 + r16;
            uint32_t ro = (uint32_t)(row * 128 + (((ks * 2 + cuA) ^ (row & 7)) << 4));
            ldsm4(ah[i], aH + ro);
            ldsm4(al[i], aL + ro);
        }
#pragma unroll
        for (int p = 0; p < 2; p++) {
            uint32_t bh[4], bl[4];
            int row = wn * 32 + p * 16 + jrow + (lane & 7);
            uint32_t ro = (uint32_t)(row * 128 + (((ks * 2 + cuB) ^ (row & 7)) << 4));
            ldsm4(bh, bH + ro);
            ldsm4(bl, bL + ro);
#pragma unroll
            for (int i = 0; i < 2; i++)
#pragma unroll
                for (int jh = 0; jh < 2; jh++) {
                    int j = p * 2 + jh;
                    const uint32_t* fh = &bh[jh * 2];
                    const uint32_t* fl = &bl[jh * 2];
                    mma16816(acc[i][j], ah[i], fh);
                    mma16816(acc[i][j], ah[i], fl);
                    mma16816(acc[i][j], al[i], fh);
                }
        }
    }
}

__device__ __forceinline__ void do_mma_v(uint32_t vA, uint32_t vB,
                                         int wm, int wn, int lane, float acc[2][4][4]) {
    int r16 = lane & 15;
    int cuA = lane >> 4;
    int cuB = (lane >> 3) & 1;
    int jrow = (lane >> 4) * 8;
#pragma unroll
    for (int ks = 0; ks < 2; ks++) {
        uint32_t ah[2][4], al[2][4];
#pragma unroll
        for (int i = 0; i < 2; i++) {
            int row = wm * 32 + i * 16 + r16;
            uint32_t roh = (uint32_t)(row * 128 + (((ks * 2 + cuA) ^ (row & 7)) << 4));
            uint32_t rol = (uint32_t)(row * 128 + (((ks * 2 + cuA + 4) ^ (row & 7)) << 4));
            ldsm4(ah[i], vA + roh);
            ldsm4(al[i], vA + rol);
        }
#pragma unroll
        for (int p = 0; p < 2; p++) {
            uint32_t bh[4], bl[4];
            int row = wn * 32 + p * 16 + jrow + (lane & 7);
            uint32_t roh = (uint32_t)(row * 128 + (((ks * 2 + cuB) ^ (row & 7)) << 4));
            uint32_t rol = (uint32_t)(row * 128 + (((ks * 2 + cuB + 4) ^ (row & 7)) << 4));
            ldsm4(bh, vB + roh);
            ldsm4(bl, vB + rol);
#pragma unroll
            for (int i = 0; i < 2; i++)
#pragma unroll
                for (int jh = 0; jh < 2; jh++) {
                    int j = p * 2 + jh;
                    const uint32_t* fh = &bh[jh * 2];
                    const uint32_t* fl = &bl[jh * 2];
                    mma16816(acc[i][j], ah[i], fh);
                    mma16816(acc[i][j], ah[i], fl);
                    mma16816(acc[i][j], al[i], fh);
                }
        }
    }
}

__global__ void __launch_bounds__(512, 1) k_main() {
    extern __shared__ __align__(1024) char smem[];
    uint32_t sb = smem_u32(smem);
    int tid = threadIdx.x, wid = tid >> 5, lane = tid & 31;
    int wm = wid & 3, wn = wid >> 2;
    float* sred = (float*)(smem + SM_SRED);

    if (tid == 0) {
        MB_INIT(sb + BAR_FULL(0), 512); MB_INIT(sb + BAR_FULL(1), 512); MB_INIT(sb + BAR_FULL(2), 512);
        MB_INIT(sb + BAR_EMPTY(0), 16); MB_INIT(sb + BAR_EMPTY(1), 16); MB_INIT(sb + BAR_EMPTY(2), 16);
        MB_INIT(sb + BAR_VFULL, 512);   MB_INIT(sb + BAR_VEMPTY, 16);
    }
    __syncthreads();

    int ntiles = (NTILEPAIRS - 1 - (int)blockIdx.x) / NSM + 1;
    int nch = ntiles * 4;

    float c0 = g_c0;
    int chain = g_chain;
    float cf0 = 0, cf1 = 0, cf2 = 0, cf3 = 0, cf4 = 0;
    if (!chain) { cf0 = g_coef[0]; cf1 = g_coef[1]; cf2 = g_coef[2]; cf3 = g_coef[3]; cf4 = g_coef[4]; }

    int prA, prB, pd;
    int crA = 0, crB = 0, cdiag = 0;
    decode_rows(blockIdx.x, &prA, &prB, &pd);

    // prologue: V(t0), chunk0 -> s0, chunk1 -> s1
    MB_WAIT(sb + BAR_VEMPTY, 1);
    FENCE_PROXY();
    issue_v(sb, prA, prB, tid);
    CP_MB_ARRIVE(sb + BAR_VFULL);
    MB_WAIT(sb + BAR_EMPTY(0), 1);
    issue_chunk(sb, SM_S + 0 * STAGE, prA, prB, 0, tid);
    CP_MB_ARRIVE(sb + BAR_FULL(0));
    MB_WAIT(sb + BAR_EMPTY(1), 1);
    issue_chunk(sb, SM_S + 1 * STAGE, prA, prB, 1, tid);
    CP_MB_ARRIVE(sb + BAR_FULL(1));

    float total = 0.f;
    float acc[2][4][4], wacc[2][4][4];

#pragma unroll 1
    for (int g = 0; g < nch; g++) {
        // ---- produce chunk g+2 ----
        int gp = g + 2;
        if (gp < nch) {
            int ps = gp % 3, pj = gp & 3;
            if (pj == 0) {
                int lt = gp >> 2;
                decode_rows((int)blockIdx.x + lt * NSM, &prA, &prB, &pd);
                MB_WAIT(sb + BAR_VEMPTY, (lt + 1) & 1);
                FENCE_PROXY();
                issue_v(sb, prA, prB, tid);
            }
            MB_WAIT(sb + BAR_EMPTY(ps), ((gp / 3) + 1) & 1);
            FENCE_PROXY();
            issue_chunk(sb, SM_S + ps * STAGE, prA, prB, pj, tid);
            CP_MB_ARRIVE(sb + BAR_FULL(ps));
            if (pj == 0) CP_MB_ARRIVE(sb + BAR_VFULL);
        }

        // ---- consume chunk g ----
        int cs = g % 3, j = g & 3;
        if (j == 0) {
            int lt = g >> 2;
            decode_rows((int)blockIdx.x + lt * NSM, &crA, &crB, &cdiag);
#pragma unroll
            for (int i = 0; i < 2; i++)
#pragma unroll
                for (int jj = 0; jj < 4; jj++)
#pragma unroll
                    for (int r = 0; r < 4; r++) { acc[i][jj][r] = 0.f; wacc[i][jj][r] = 0.f; }

            MB_WAIT(sb + BAR_VFULL, lt & 1);
            do_mma_v(sb + SM_VA, sb + SM_VB, wm, wn, lane, wacc);
            if (lane == 0) MB_ARRIVE(sb + BAR_VEMPTY);
        }

        MB_WAIT(sb + BAR_FULL(cs), (g / 3) & 1);
        uint32_t st = sb + SM_S + cs * STAGE;
        do_mma(st, st + 16384, st + 32768, st + 49152, wm, wn, lane, acc);
        if (lane == 0) MB_ARRIVE(sb + BAR_EMPTY(cs));

        if (j == 3) {
            // sq loads at epilogue (L2-resident; keeps mainloop registers free)
            float sqa_r[4], sqb_c[8];
#pragma unroll
            for (int i = 0; i < 2; i++)
#pragma unroll
                for (int rh = 0; rh < 2; rh++)
                    sqa_r[i * 2 + rh] = g_sq[crA + wm * 32 + i * 16 + (lane >> 2) + rh * 8];
#pragma unroll
            for (int jj = 0; jj < 4; jj++)
#pragma unroll
                for (int cc2 = 0; cc2 < 2; cc2++)
                    sqb_c[jj * 2 + cc2] = g_sq[crB + wn * 32 + jj * 8 + (lane & 3) * 2 + cc2];

            float part = 0.f;
#pragma unroll
            for (int i = 0; i < 2; i++)
#pragma unroll
                for (int jj = 0; jj < 4; jj++)
#pragma unroll
                    for (int r = 0; r < 4; r++) {
                        float l2 = fmaf(-2.0f, acc[i][jj][r],
                                        sqa_r[i * 2 + (r >> 1)] + sqb_c[jj * 2 + (r & 1)]);
                        l2 = fmaxf(l2, 0.0f);
                        float ks;
                        if (chain) {
                            float x  = ex2f(-l2 * c0);
                            float x2 = x * x, x4 = x2 * x2, x8 = x4 * x4;
                            ks = x + x2 + x4 + x8 + x8 * x8;
                        } else {
                            ks = ex2f(-l2 * cf0) + ex2f(-l2 * cf1) + ex2f(-l2 * cf2)
                               + ex2f(-l2 * cf3) + ex2f(-l2 * cf4);
                        }
                        part = fmaf(ks, wacc[i][jj][r], part);
                    }
            if (!cdiag) part *= 2.0f;
            total += part;
        }
    }

    // ---- one reduction + atomic per CTA ----
#pragma unroll
    for (int off = 16; off; off >>= 1) total += __shfl_xor_sync(0xffffffffu, total, off);
    if (lane == 0) sred[wid] = total;
    __syncthreads();
    if (tid == 0) {
        float s = 0.f;
#pragma unroll
        for (int w = 0; w < 16; w++) s += sred[w];
        atomicAdd(&g_loss, (double)s);
    }
}

__global__ void k_out(float* out) {
    out[0] = (float)(g_loss * (double)g_inv_nidx);
}

// ======================= launch =======================
extern "C" void kernel_launch(void* const* d_in, const int* in_sizes, int n_in,
                              void* d_out, int out_size) {
    const float* src = (const float*)d_in[0];
    const float* tgt = (const float*)d_in[1];
    const int*   sl  = (const int*)d_in[2];
    const float* tl  = (const float*)d_in[3];
    float* out = (float*)d_out;

    cudaFuncSetAttribute(k_main, cudaFuncAttributeMaxDynamicSharedMemorySize, SMEM_TOTAL);

    k_prep<<<1024, 256>>>(src, tgt, sl, tl);
    k_reduce<<<96, 256>>>();
    k_finalize<<<1, 256>>>();
    k_buildV<<<1024, 256>>>(sl, tl);
    k_main<<<NSM, 512, SMEM_TOTAL>>>();
    k_out<<<1, 1>>>(out);
}